// round 8
// baseline (speedup 1.0000x reference)
#include <cuda_runtime.h>
#include <cuda_bf16.h>
#include <cstdint>

#define BATCH 2
#define SEQ 2048
#define NEMBD 1024
#define NHEAD 16
#define HDIM 64
#define WINDOW 256
#define ATT_SCALE 0.125f   // 1/sqrt(64)

// ---------------- device scratch (allocation-free rule) ----------------
__device__ __nv_bfloat16 g_kvh[(size_t)4096 * 3072];           // qkv hi
__device__ __nv_bfloat16 g_kvl[(size_t)4096 * 3072];           // qkv lo
__device__ __nv_bfloat16 g_ah[(size_t)4096 * 1024];            // hidden hi
__device__ __nv_bfloat16 g_al[(size_t)4096 * 1024];            // hidden lo
__device__ __nv_bfloat16 g_wh[(size_t)3072 * 1024];            // w_attn^T hi [N][K]
__device__ __nv_bfloat16 g_wl[(size_t)3072 * 1024];
__device__ __nv_bfloat16 g_ph[(size_t)1024 * 1024];            // w_proj^T hi
__device__ __nv_bfloat16 g_pl[(size_t)1024 * 1024];
__device__ __nv_bfloat16 g_oh[(size_t)4096 * 1024];            // attn out hi
__device__ __nv_bfloat16 g_ol[(size_t)4096 * 1024];

// ---------------- helpers ----------------
__device__ __forceinline__ uint32_t smem_u32(const void* p) {
    uint32_t a;
    asm("{ .reg .u64 t; cvta.to.shared.u64 t, %1; cvt.u32.u64 %0, t; }"
        : "=r"(a) : "l"(p));
    return a;
}
__device__ __forceinline__ void split4(float4 v, uint2& hi, uint2& lo) {
    __nv_bfloat162 h01 = __floats2bfloat162_rn(v.x, v.y);
    __nv_bfloat162 h23 = __floats2bfloat162_rn(v.z, v.w);
    float l0 = v.x - __low2float(h01), l1 = v.y - __high2float(h01);
    float l2 = v.z - __low2float(h23), l3 = v.w - __high2float(h23);
    __nv_bfloat162 lo01 = __floats2bfloat162_rn(l0, l1);
    __nv_bfloat162 lo23 = __floats2bfloat162_rn(l2, l3);
    hi.x = *(uint32_t*)&h01; hi.y = *(uint32_t*)&h23;
    lo.x = *(uint32_t*)&lo01; lo.y = *(uint32_t*)&lo23;
}
__device__ __forceinline__ void split2(float a, float b, uint32_t& hi, uint32_t& lo) {
    __nv_bfloat162 h = __floats2bfloat162_rn(a, b);
    float ra = a - __low2float(h), rb = b - __high2float(h);
    __nv_bfloat162 L = __floats2bfloat162_rn(ra, rb);
    hi = *(uint32_t*)&h; lo = *(uint32_t*)&L;
}
__device__ __forceinline__ void mma16816(float* c, const uint32_t* a, const uint32_t* b) {
    asm volatile(
        "mma.sync.aligned.m16n8k16.row.col.f32.bf16.bf16.f32 "
        "{%0,%1,%2,%3},{%4,%5,%6,%7},{%8,%9},{%0,%1,%2,%3};"
        : "+f"(c[0]), "+f"(c[1]), "+f"(c[2]), "+f"(c[3])
        : "r"(a[0]), "r"(a[1]), "r"(a[2]), "r"(a[3]), "r"(b[0]), "r"(b[1]));
}
__device__ __forceinline__ void ldsm4(uint32_t* r, uint32_t addr) {
    asm volatile("ldmatrix.sync.aligned.m8n8.x4.shared.b16 {%0,%1,%2,%3}, [%4];"
                 : "=r"(r[0]), "=r"(r[1]), "=r"(r[2]), "=r"(r[3]) : "r"(addr));
}
__device__ __forceinline__ void ldsm4t(uint32_t* r, uint32_t addr) {
    asm volatile("ldmatrix.sync.aligned.m8n8.x4.trans.shared.b16 {%0,%1,%2,%3}, [%4];"
                 : "=r"(r[0]), "=r"(r[1]), "=r"(r[2]), "=r"(r[3]) : "r"(addr));
}
__device__ __forceinline__ void cpa16(uint32_t saddr, const void* gaddr) {
    asm volatile("cp.async.cg.shared.global [%0], [%1], 16;" :: "r"(saddr), "l"(gaddr));
}
#define CP_COMMIT() asm volatile("cp.async.commit_group;")
#define CP_WAIT1()  asm volatile("cp.async.wait_group 1;")

// SW128 swizzle for 128B rows
__device__ __forceinline__ uint32_t swz(int row, int col) {
    return (uint32_t)(row * 128 + (col ^ ((row & 7) << 4)));
}
__device__ __forceinline__ float qmax(float v) {
    v = fmaxf(v, __shfl_xor_sync(0xFFFFFFFFu, v, 1));
    v = fmaxf(v, __shfl_xor_sync(0xFFFFFFFFu, v, 2));
    return v;
}
__device__ __forceinline__ float qsum(float v) {
    v += __shfl_xor_sync(0xFFFFFFFFu, v, 1);
    v += __shfl_xor_sync(0xFFFFFFFFu, v, 2);
    return v;
}

// ===========================================================================
// conversion kernels
// ===========================================================================
__global__ void split_kernel(const float* __restrict__ src,
                             __nv_bfloat16* __restrict__ hi,
                             __nv_bfloat16* __restrict__ lo, int n4) {
    int i = blockIdx.x * blockDim.x + threadIdx.x;
    if (i < n4) {
        float4 v = *(const float4*)(src + (size_t)i * 4);
        uint2 h, l; split4(v, h, l);
        *(uint2*)(hi + (size_t)i * 4) = h;
        *(uint2*)(lo + (size_t)i * 4) = l;
    }
}
__global__ void split_tr_kernel(const float* __restrict__ src,
                                __nv_bfloat16* __restrict__ hi,
                                __nv_bfloat16* __restrict__ lo, int K, int N) {
    __shared__ float t[32][33];
    const int n0 = blockIdx.x * 32, k0 = blockIdx.y * 32;
    const int tx = threadIdx.x, ty = threadIdx.y;   // 32 x 8
#pragma unroll
    for (int i = 0; i < 4; i++)
        t[ty + i * 8][tx] = src[(size_t)(k0 + ty + i * 8) * N + n0 + tx];
    __syncthreads();
#pragma unroll
    for (int i = 0; i < 4; i++) {
        int n = ty + i * 8;
        float v = t[tx][n];
        __nv_bfloat16 h = __float2bfloat16(v);
        float l = v - __bfloat162float(h);
        hi[(size_t)(n0 + n) * K + k0 + tx] = h;
        lo[(size_t)(n0 + n) * K + k0 + tx] = __float2bfloat16(l);
    }
}

// ===========================================================================
// split-precision bf16 GEMM: C = A@B^T + bias
// CTA 128x128, BK=64, 2-stage cp.async, SW128, ldmatrix.
// 512 threads = 16 warps, warp tile 32x32 (4x4 grid) -> 4 warps/SMSP.
// If Ch != null, writes split bf16 hi/lo instead of fp32 C.
// ===========================================================================
#define ST_AH 0
#define ST_AL 16384
#define ST_BH 32768
#define ST_BL 49152
#define ST_SZ 65536
#define GSMEM (2 * ST_SZ)

__global__ __launch_bounds__(512, 1)
void gemm_bf16_kernel(const __nv_bfloat16* __restrict__ Ah, const __nv_bfloat16* __restrict__ Al,
                      const __nv_bfloat16* __restrict__ Bh, const __nv_bfloat16* __restrict__ Bl,
                      const float* __restrict__ bias, float* __restrict__ C,
                      __nv_bfloat16* __restrict__ Ch, __nv_bfloat16* __restrict__ Cl,
                      int M, int N, int K) {
    extern __shared__ char sm[];
    const uint32_t sb = smem_u32(sm);
    const int tid = threadIdx.x, lane = tid & 31, wid = tid >> 5;
    const int m0 = blockIdx.y * 128, n0 = blockIdx.x * 128;
    const int wm = wid >> 2, wn = wid & 3;          // 4 x 4 warp grid, tile 32x32
    const int l15 = lane & 15, chi = (lane >> 4) * 16;
    const int NT = K / 64;

    float acc[2][4][4];
#pragma unroll
    for (int i = 0; i < 2; i++)
#pragma unroll
        for (int j = 0; j < 4; j++)
#pragma unroll
            for (int r = 0; r < 4; r++) acc[i][j][r] = 0.f;

    // cp.async: 1024 16B-chunks per buffer, 2 per thread
    const int crow = tid >> 2;                      // 0..127
    const int cc0  = (tid & 3) * 2;                 // 0,2,4,6
    const int cc1  = cc0 + 1;

    auto load_stage = [&](int s, int kt) {
        const uint32_t sbase = sb + s * ST_SZ;
        const size_t g0 = (size_t)kt * 64 + cc0 * 8;
        const size_t g1 = (size_t)kt * 64 + cc1 * 8;
        const uint32_t so0 = swz(crow, cc0 * 16);
        const uint32_t so1 = swz(crow, cc1 * 16);
        const size_t ar = (size_t)(m0 + crow) * K;
        const size_t br = (size_t)(n0 + crow) * K;
        cpa16(sbase + ST_AH + so0, Ah + ar + g0);
        cpa16(sbase + ST_AH + so1, Ah + ar + g1);
        cpa16(sbase + ST_AL + so0, Al + ar + g0);
        cpa16(sbase + ST_AL + so1, Al + ar + g1);
        cpa16(sbase + ST_BH + so0, Bh + br + g0);
        cpa16(sbase + ST_BH + so1, Bh + br + g1);
        cpa16(sbase + ST_BL + so0, Bl + br + g0);
        cpa16(sbase + ST_BL + so1, Bl + br + g1);
    };

    load_stage(0, 0); CP_COMMIT();
    load_stage(1, 1); CP_COMMIT();

    for (int t = 0; t < NT; t++) {
        const int s = t & 1;
        CP_WAIT1();
        __syncthreads();

        const uint32_t abase = sb + s * ST_SZ;
#pragma unroll
        for (int ks = 0; ks < 4; ks++) {
            const int cb = ks * 32 + chi;
            uint32_t Afh[2][4], Bfh[2][4], Afl[2][4], Bfl[2][4];
#pragma unroll
            for (int mt = 0; mt < 2; mt++)
                ldsm4(Afh[mt], abase + ST_AH + swz(wm * 32 + mt * 16 + l15, cb));
#pragma unroll
            for (int bt = 0; bt < 2; bt++)
                ldsm4(Bfh[bt], abase + ST_BH + swz(wn * 32 + bt * 16 + l15, cb));
            // pass 1: Ah * Bh
#pragma unroll
            for (int mt = 0; mt < 2; mt++)
#pragma unroll
                for (int nt = 0; nt < 4; nt++) {
                    uint32_t b[2] = { Bfh[nt >> 1][nt & 1], Bfh[nt >> 1][(nt & 1) + 2] };
                    mma16816(acc[mt][nt], Afh[mt], b);
                }
            // pass 2: Ah * Bl
#pragma unroll
            for (int bt = 0; bt < 2; bt++)
                ldsm4(Bfl[bt], abase + ST_BL + swz(wn * 32 + bt * 16 + l15, cb));
#pragma unroll
            for (int mt = 0; mt < 2; mt++)
#pragma unroll
                for (int nt = 0; nt < 4; nt++) {
                    uint32_t b[2] = { Bfl[nt >> 1][nt & 1], Bfl[nt >> 1][(nt & 1) + 2] };
                    mma16816(acc[mt][nt], Afh[mt], b);
                }
            // pass 3: Al * Bh
#pragma unroll
            for (int mt = 0; mt < 2; mt++)
                ldsm4(Afl[mt], abase + ST_AL + swz(wm * 32 + mt * 16 + l15, cb));
#pragma unroll
            for (int mt = 0; mt < 2; mt++)
#pragma unroll
                for (int nt = 0; nt < 4; nt++) {
                    uint32_t b[2] = { Bfh[nt >> 1][nt & 1], Bfh[nt >> 1][(nt & 1) + 2] };
                    mma16816(acc[mt][nt], Afl[mt], b);
                }
        }
        __syncthreads();
        if (t + 2 < NT) { load_stage(s, t + 2); CP_COMMIT(); }
    }

    const int g = lane >> 2, tig = lane & 3;
#pragma unroll
    for (int mt = 0; mt < 2; mt++) {
#pragma unroll
        for (int nt = 0; nt < 4; nt++) {
            int row0 = m0 + wm * 32 + mt * 16 + g;
            int col  = n0 + wn * 32 + nt * 8 + tig * 2;
            float2 bb = *(const float2*)(bias + col);
            float x0 = acc[mt][nt][0] + bb.x, x1 = acc[mt][nt][1] + bb.y;
            float x2 = acc[mt][nt][2] + bb.x, x3 = acc[mt][nt][3] + bb.y;
            if (Ch) {
                uint32_t h, l;
                split2(x0, x1, h, l);
                *(uint32_t*)(Ch + (size_t)row0 * N + col) = h;
                *(uint32_t*)(Cl + (size_t)row0 * N + col) = l;
                split2(x2, x3, h, l);
                *(uint32_t*)(Ch + (size_t)(row0 + 8) * N + col) = h;
                *(uint32_t*)(Cl + (size_t)(row0 + 8) * N + col) = l;
            } else {
                *(float2*)(C + (size_t)row0 * N + col)       = make_float2(x0, x1);
                *(float2*)(C + (size_t)(row0 + 8) * N + col) = make_float2(x2, x3);
            }
        }
    }
}

// ===========================================================================
// Flash attention via mma.sync with split-bf16 precision (unchanged from R7).
// ===========================================================================
#define A_KH 0
#define A_KL 8192
#define A_VH 16384
#define A_VL 24576
#define A_SMEM 32768

__global__ __launch_bounds__(128)
void attn_mma_kernel(const __nv_bfloat16* __restrict__ qh,
                     const __nv_bfloat16* __restrict__ ql,
                     __nv_bfloat16* __restrict__ oh, __nv_bfloat16* __restrict__ ol) {
    extern __shared__ char sm[];
    const uint32_t sb = smem_u32(sm);
    const int b = blockIdx.z, h = blockIdx.y, qs = blockIdx.x * 64;
    const int tid = threadIdx.x, lane = tid & 31, wid = tid >> 5;
    const int l15 = lane & 15, chi = (lane >> 4) * 16;
    const int g = lane >> 2, tig = lane & 3;
    const size_t RS = 3 * NEMBD;
    const int hcol = h * HDIM;

    {
#pragma unroll
        for (int i = 0; i < 8; i++) {
            int idx = tid + i * 128;
            int buf = idx >> 9;
            int rem = idx & 511;
            int r = rem >> 3, c = rem & 7;
            const __nv_bfloat16* src = (buf == 0 ? qh : ql)
                + ((size_t)(b * SEQ + qs + r)) * RS + hcol + c * 8;
            *(uint4*)(sm + (buf == 0 ? A_KH : A_KL) + swz(r, c * 16)) = *(const uint4*)src;
        }
    }
    __syncthreads();
    uint32_t Qfh[4][4], Qfl[4][4];
#pragma unroll
    for (int kk = 0; kk < 4; kk++) {
        ldsm4(Qfh[kk], sb + A_KH + swz(wid * 16 + l15, kk * 32 + chi));
        ldsm4(Qfl[kk], sb + A_KL + swz(wid * 16 + l15, kk * 32 + chi));
    }
    __syncthreads();

    float o[8][4];
#pragma unroll
    for (int i = 0; i < 8; i++)
#pragma unroll
        for (int r = 0; r < 4; r++) o[i][r] = 0.f;
    float m0 = -1e30f, m1 = -1e30f, l0 = 0.f, l1 = 0.f;
    const int row0 = qs + wid * 16 + g, row1 = row0 + 8;

    int kt0 = qs - WINDOW; if (kt0 < 0) kt0 = 0;

    for (int kt = kt0; kt <= qs; kt += 64) {
#pragma unroll
        for (int i = 0; i < 16; i++) {
            int idx = tid + i * 128;
            int buf = idx >> 9;
            int rem = idx & 511;
            int r = rem >> 3, c = rem & 7;
            const __nv_bfloat16* base = ((buf & 1) == 0) ? qh : ql;
            int coff = (buf < 2) ? NEMBD : 2 * NEMBD;
            const __nv_bfloat16* src = base
                + ((size_t)(b * SEQ + kt + r)) * RS + coff + hcol + c * 8;
            uint32_t dst = (buf == 0 ? A_KH : buf == 1 ? A_KL : buf == 2 ? A_VH : A_VL);
            *(uint4*)(sm + dst + swz(r, c * 16)) = *(const uint4*)src;
        }
        __syncthreads();

        float s[8][4];
#pragma unroll
        for (int i = 0; i < 8; i++)
#pragma unroll
            for (int r = 0; r < 4; r++) s[i][r] = 0.f;
#pragma unroll
        for (int kk = 0; kk < 4; kk++) {
            const int cb = kk * 32 + chi;
            uint32_t Kfh[4][4], Kfl[4][4];
#pragma unroll
            for (int bt = 0; bt < 4; bt++) {
                ldsm4(Kfh[bt], sb + A_KH + swz(bt * 16 + l15, cb));
                ldsm4(Kfl[bt], sb + A_KL + swz(bt * 16 + l15, cb));
            }
#pragma unroll
            for (int nt = 0; nt < 8; nt++) {
                uint32_t bh[2] = { Kfh[nt >> 1][nt & 1], Kfh[nt >> 1][(nt & 1) + 2] };
                uint32_t bl[2] = { Kfl[nt >> 1][nt & 1], Kfl[nt >> 1][(nt & 1) + 2] };
                mma16816(s[nt], Qfh[kk], bh);
                mma16816(s[nt], Qfh[kk], bl);
                mma16816(s[nt], Qfl[kk], bh);
            }
        }

        float mx0 = -1e30f, mx1 = -1e30f;
#pragma unroll
        for (int nt = 0; nt < 8; nt++) {
            int j0 = kt + nt * 8 + tig * 2, j1 = j0 + 1;
            float v;
            v = fminf(fmaxf(s[nt][0] * ATT_SCALE, -10000.f), 10000.f);
            v = (j0 <= row0 && j0 > row0 - WINDOW) ? v : -1e30f;
            s[nt][0] = v; mx0 = fmaxf(mx0, v);
            v = fminf(fmaxf(s[nt][1] * ATT_SCALE, -10000.f), 10000.f);
            v = (j1 <= row0 && j1 > row0 - WINDOW) ? v : -1e30f;
            s[nt][1] = v; mx0 = fmaxf(mx0, v);
            v = fminf(fmaxf(s[nt][2] * ATT_SCALE, -10000.f), 10000.f);
            v = (j0 <= row1 && j0 > row1 - WINDOW) ? v : -1e30f;
            s[nt][2] = v; mx1 = fmaxf(mx1, v);
            v = fminf(fmaxf(s[nt][3] * ATT_SCALE, -10000.f), 10000.f);
            v = (j1 <= row1 && j1 > row1 - WINDOW) ? v : -1e30f;
            s[nt][3] = v; mx1 = fmaxf(mx1, v);
        }
        mx0 = qmax(mx0); mx1 = qmax(mx1);
        const float m0n = fmaxf(m0, mx0), m1n = fmaxf(m1, mx1);
        const float c0 = __expf(m0 - m0n), c1 = __expf(m1 - m1n);

        uint32_t ph01[8], ph23[8], pl01[8], pl23[8];
        float sum0 = 0.f, sum1 = 0.f;
#pragma unroll
        for (int nt = 0; nt < 8; nt++) {
            float p0 = __expf(s[nt][0] - m0n), p1 = __expf(s[nt][1] - m0n);
            float p2 = __expf(s[nt][2] - m1n), p3 = __expf(s[nt][3] - m1n);
            sum0 += p0 + p1; sum1 += p2 + p3;
            split2(p0, p1, ph01[nt], pl01[nt]);
            split2(p2, p3, ph23[nt], pl23[nt]);
        }
        sum0 = qsum(sum0); sum1 = qsum(sum1);
        l0 = l0 * c0 + sum0; l1 = l1 * c1 + sum1;
        m0 = m0n; m1 = m1n;
#pragma unroll
        for (int i = 0; i < 8; i++) {
            o[i][0] *= c0; o[i][1] *= c0; o[i][2] *= c1; o[i][3] *= c1;
        }

#pragma unroll
        for (int kk = 0; kk < 4; kk++) {
            uint32_t ah[4] = { ph01[2 * kk], ph23[2 * kk], ph01[2 * kk + 1], ph23[2 * kk + 1] };
            uint32_t al[4] = { pl01[2 * kk], pl23[2 * kk], pl01[2 * kk + 1], pl23[2 * kk + 1] };
            uint32_t Vfh[4][4], Vfl[4][4];
#pragma unroll
            for (int db = 0; db < 4; db++) {
                ldsm4t(Vfh[db], sb + A_VH + swz(kk * 16 + l15, db * 32 + chi));
                ldsm4t(Vfl[db], sb + A_VL + swz(kk * 16 + l15, db * 32 + chi));
            }
#pragma unroll
            for (int dnt = 0; dnt < 8; dnt++) {
                uint32_t bh[2] = { Vfh[dnt >> 1][(dnt & 1) * 2], Vfh[dnt >> 1][(dnt & 1) * 2 + 1] };
                uint32_t bl[2] = { Vfl[dnt >> 1][(dnt & 1) * 2], Vfl[dnt >> 1][(dnt & 1) * 2 + 1] };
                mma16816(o[dnt], ah, bh);
                mma16816(o[dnt], ah, bl);
                mma16816(o[dnt], al, bh);
            }
        }
        __syncthreads();
    }

    const float i0 = 1.f / l0, i1 = 1.f / l1;
    const size_t tok0 = (size_t)(b * SEQ) + row0;
#pragma unroll
    for (int dnt = 0; dnt < 8; dnt++) {
        int col = hcol + dnt * 8 + tig * 2;
        uint32_t hv, lv;
        split2(o[dnt][0] * i0, o[dnt][1] * i0, hv, lv);
        *(uint32_t*)(oh + tok0 * NEMBD + col) = hv;
        *(uint32_t*)(ol + tok0 * NEMBD + col) = lv;
        split2(o[dnt][2] * i1, o[dnt][3] * i1, hv, lv);
        *(uint32_t*)(oh + (tok0 + 8) * NEMBD + col) = hv;
        *(uint32_t*)(ol + (tok0 + 8) * NEMBD + col) = lv;
    }
}

// ---------------------------------------------------------------------------
extern "C" void kernel_launch(void* const* d_in, const int* in_sizes, int n_in,
                              void* d_out, int out_size) {
    const float* hidden = (const float*)d_in[0];
    const float* w_attn = (const float*)d_in[1];
    const float* b_attn = (const float*)d_in[2];
    const float* w_proj = (const float*)d_in[3];
    const float* b_proj = (const float*)d_in[4];
    float* out = (float*)d_out;

    __nv_bfloat16 *kvh, *kvl, *ah, *al, *wh, *wl, *ph, *pl, *oh, *ol;
    cudaGetSymbolAddress((void**)&kvh, g_kvh); cudaGetSymbolAddress((void**)&kvl, g_kvl);
    cudaGetSymbolAddress((void**)&ah, g_ah); cudaGetSymbolAddress((void**)&al, g_al);
    cudaGetSymbolAddress((void**)&wh, g_wh); cudaGetSymbolAddress((void**)&wl, g_wl);
    cudaGetSymbolAddress((void**)&ph, g_ph); cudaGetSymbolAddress((void**)&pl, g_pl);
    cudaGetSymbolAddress((void**)&oh, g_oh); cudaGetSymbolAddress((void**)&ol, g_ol);

    const int M = BATCH * SEQ;       // 4096
    const int E = NEMBD;             // 1024

    cudaFuncSetAttribute(gemm_bf16_kernel,
                         cudaFuncAttributeMaxDynamicSharedMemorySize, GSMEM);
    cudaFuncSetAttribute(attn_mma_kernel,
                         cudaFuncAttributeMaxDynamicSharedMemorySize, A_SMEM);

    // 0) splits
    {
        int n4 = M * E / 4;
        split_kernel<<<(n4 + 255) / 256, 256>>>(hidden, ah, al, n4);
    }
    split_tr_kernel<<<dim3(3 * E / 32, E / 32), dim3(32, 8)>>>(w_attn, wh, wl, E, 3 * E);
    split_tr_kernel<<<dim3(E / 32, E / 32), dim3(32, 8)>>>(w_proj, ph, pl, E, E);

    // 1) QKV projection -> split bf16 qkv
    gemm_bf16_kernel<<<dim3(3 * E / 128, M / 128), 512, GSMEM>>>(
        ah, al, wh, wl, b_attn, nullptr, kvh, kvl, M, 3 * E, E);
    // 2) flash attention (tensor cores) -> split bf16
    attn_mma_kernel<<<dim3(SEQ / 64, NHEAD, BATCH), 128, A_SMEM>>>(kvh, kvl, oh, ol);
    // 3) output projection -> fp32
    gemm_bf16_kernel<<<dim3(E / 128, M / 128), 512, GSMEM>>>(
        oh, ol, ph, pl, b_proj, out, nullptr, nullptr, M, E, E);
}

// round 9
// speedup vs baseline: 1.4940x; 1.4940x over previous
#include <cuda_runtime.h>
#include <cuda_fp16.h>
#include <cstdint>

#define BATCH 2
#define SEQ 2048
#define NEMBD 1024
#define NHEAD 16
#define HDIM 64
#define WINDOW 256
#define ATT_SCALE 0.125f   // 1/sqrt(64)

// ---------------- device scratch (allocation-free rule) ----------------
__device__ __half g_kvh[(size_t)4096 * 3072];      // qkv hi (fp16)
__device__ __half g_kvl[(size_t)4096 * 3072];      // qkv lo
__device__ __half g_ah[(size_t)4096 * 1024];       // hidden fp16 (single)
__device__ __half g_wh[(size_t)3072 * 1024];       // w_attn^T hi [N][K]
__device__ __half g_wl[(size_t)3072 * 1024];
__device__ __half g_ph[(size_t)1024 * 1024];       // w_proj^T hi
__device__ __half g_pl[(size_t)1024 * 1024];
__device__ __half g_oh[(size_t)4096 * 1024];       // attn out fp16 (single)

// ---------------- helpers ----------------
__device__ __forceinline__ uint32_t smem_u32(const void* p) {
    uint32_t a;
    asm("{ .reg .u64 t; cvta.to.shared.u64 t, %1; cvt.u32.u64 %0, t; }"
        : "=r"(a) : "l"(p));
    return a;
}
__device__ __forceinline__ void split2h(float a, float b, uint32_t& hi, uint32_t& lo) {
    __half2 h = __floats2half2_rn(a, b);
    float ra = a - __half2float(__low2half(h));
    float rb = b - __half2float(__high2half(h));
    __half2 L = __floats2half2_rn(ra, rb);
    hi = *(uint32_t*)&h; lo = *(uint32_t*)&L;
}
__device__ __forceinline__ uint32_t pkh2(float a, float b) {
    __half2 h = __floats2half2_rn(a, b);
    return *(uint32_t*)&h;
}
__device__ __forceinline__ void mma16816h(float* c, const uint32_t* a, const uint32_t* b) {
    asm volatile(
        "mma.sync.aligned.m16n8k16.row.col.f32.f16.f16.f32 "
        "{%0,%1,%2,%3},{%4,%5,%6,%7},{%8,%9},{%0,%1,%2,%3};"
        : "+f"(c[0]), "+f"(c[1]), "+f"(c[2]), "+f"(c[3])
        : "r"(a[0]), "r"(a[1]), "r"(a[2]), "r"(a[3]), "r"(b[0]), "r"(b[1]));
}
__device__ __forceinline__ void ldsm4(uint32_t* r, uint32_t addr) {
    asm volatile("ldmatrix.sync.aligned.m8n8.x4.shared.b16 {%0,%1,%2,%3}, [%4];"
                 : "=r"(r[0]), "=r"(r[1]), "=r"(r[2]), "=r"(r[3]) : "r"(addr));
}
__device__ __forceinline__ void ldsm4t(uint32_t* r, uint32_t addr) {
    asm volatile("ldmatrix.sync.aligned.m8n8.x4.trans.shared.b16 {%0,%1,%2,%3}, [%4];"
                 : "=r"(r[0]), "=r"(r[1]), "=r"(r[2]), "=r"(r[3]) : "r"(addr));
}
__device__ __forceinline__ void cpa16(uint32_t saddr, const void* gaddr) {
    asm volatile("cp.async.cg.shared.global [%0], [%1], 16;" :: "r"(saddr), "l"(gaddr));
}
#define CP_COMMIT() asm volatile("cp.async.commit_group;")
#define CP_WAIT1()  asm volatile("cp.async.wait_group 1;")

// SW128 swizzle for 128B rows
__device__ __forceinline__ uint32_t swz(int row, int col) {
    return (uint32_t)(row * 128 + (col ^ ((row & 7) << 4)));
}
__device__ __forceinline__ float qmax(float v) {
    v = fmaxf(v, __shfl_xor_sync(0xFFFFFFFFu, v, 1));
    v = fmaxf(v, __shfl_xor_sync(0xFFFFFFFFu, v, 2));
    return v;
}
__device__ __forceinline__ float qsum(float v) {
    v += __shfl_xor_sync(0xFFFFFFFFu, v, 1);
    v += __shfl_xor_sync(0xFFFFFFFFu, v, 2);
    return v;
}

// ===========================================================================
// conversion kernels
// ===========================================================================
__global__ void cvt_h_kernel(const float* __restrict__ src,
                             __half* __restrict__ dst, int n4) {
    int i = blockIdx.x * blockDim.x + threadIdx.x;
    if (i < n4) {
        float4 v = *(const float4*)(src + (size_t)i * 4);
        __half2 h01 = __floats2half2_rn(v.x, v.y);
        __half2 h23 = __floats2half2_rn(v.z, v.w);
        uint2 o; o.x = *(uint32_t*)&h01; o.y = *(uint32_t*)&h23;
        *(uint2*)(dst + (size_t)i * 4) = o;
    }
}
// src [K,N] fp32 row-major -> dst [N][K] fp16 hi/lo
__global__ void split_tr_h_kernel(const float* __restrict__ src,
                                  __half* __restrict__ hi,
                                  __half* __restrict__ lo, int K, int N) {
    __shared__ float t[32][33];
    const int n0 = blockIdx.x * 32, k0 = blockIdx.y * 32;
    const int tx = threadIdx.x, ty = threadIdx.y;   // 32 x 8
#pragma unroll
    for (int i = 0; i < 4; i++)
        t[ty + i * 8][tx] = src[(size_t)(k0 + ty + i * 8) * N + n0 + tx];
    __syncthreads();
#pragma unroll
    for (int i = 0; i < 4; i++) {
        int n = ty + i * 8;
        float v = t[tx][n];
        __half h = __float2half_rn(v);
        float l = v - __half2float(h);
        hi[(size_t)(n0 + n) * K + k0 + tx] = h;
        lo[(size_t)(n0 + n) * K + k0 + tx] = __float2half_rn(l);
    }
}

// ===========================================================================
// 2-pass fp16 GEMM: C = A@B^T + bias;  A single fp16, B split hi/lo fp16.
// CTA 128x128, BK=64, 2-stage cp.async, SW128, 256 threads, warp tile 64x32.
// If Ch != null, writes split fp16 hi/lo instead of fp32 C.
// ===========================================================================
#define ST_A  0
#define ST_BH 16384
#define ST_BL 32768
#define ST_SZ 49152
#define GSMEM (2 * ST_SZ)

__global__ __launch_bounds__(256, 1)
void gemm_h_kernel(const __half* __restrict__ A,
                   const __half* __restrict__ Bh, const __half* __restrict__ Bl,
                   const float* __restrict__ bias, float* __restrict__ C,
                   __half* __restrict__ Ch, __half* __restrict__ Cl,
                   int M, int N, int K) {
    extern __shared__ char sm[];
    const uint32_t sb = smem_u32(sm);
    const int tid = threadIdx.x, lane = tid & 31, wid = tid >> 5;
    const int m0 = blockIdx.y * 128, n0 = blockIdx.x * 128;
    const int wm = wid >> 2, wn = wid & 3;          // 2 x 4 warp grid, tile 64x32
    const int l15 = lane & 15, chi = (lane >> 4) * 16;
    const int lrow = tid >> 3, lc = tid & 7;
    const int NT = K / 64;

    float acc[4][4][4];
#pragma unroll
    for (int i = 0; i < 4; i++)
#pragma unroll
        for (int j = 0; j < 4; j++)
#pragma unroll
            for (int r = 0; r < 4; r++) acc[i][j][r] = 0.f;

    auto load_stage = [&](int s, int kt) {
        const uint32_t sbase = sb + s * ST_SZ;
        const size_t gk = (size_t)kt * 64 + lc * 8;
#pragma unroll
        for (int i = 0; i < 4; i++) {
            const int row = lrow + i * 32;
            const uint32_t so = swz(row, lc * 16);
            cpa16(sbase + ST_A  + so, A  + (size_t)(m0 + row) * K + gk);
            cpa16(sbase + ST_BH + so, Bh + (size_t)(n0 + row) * K + gk);
            cpa16(sbase + ST_BL + so, Bl + (size_t)(n0 + row) * K + gk);
        }
    };

    load_stage(0, 0); CP_COMMIT();
    load_stage(1, 1); CP_COMMIT();

    for (int t = 0; t < NT; t++) {
        const int s = t & 1;
        CP_WAIT1();
        __syncthreads();

        const uint32_t abase = sb + s * ST_SZ;
#pragma unroll
        for (int ks = 0; ks < 4; ks++) {
            const int cb = ks * 32 + chi;
            uint32_t Af[4][4], Bfh[2][4], Bfl[2][4];
#pragma unroll
            for (int mt = 0; mt < 4; mt++)
                ldsm4(Af[mt], abase + ST_A + swz(wm * 64 + mt * 16 + l15, cb));
#pragma unroll
            for (int bt = 0; bt < 2; bt++)
                ldsm4(Bfh[bt], abase + ST_BH + swz(wn * 32 + bt * 16 + l15, cb));
            // pass 1: A * Bh
#pragma unroll
            for (int mt = 0; mt < 4; mt++)
#pragma unroll
                for (int nt = 0; nt < 4; nt++) {
                    uint32_t b[2] = { Bfh[nt >> 1][nt & 1], Bfh[nt >> 1][(nt & 1) + 2] };
                    mma16816h(acc[mt][nt], Af[mt], b);
                }
            // pass 2: A * Bl
#pragma unroll
            for (int bt = 0; bt < 2; bt++)
                ldsm4(Bfl[bt], abase + ST_BL + swz(wn * 32 + bt * 16 + l15, cb));
#pragma unroll
            for (int mt = 0; mt < 4; mt++)
#pragma unroll
                for (int nt = 0; nt < 4; nt++) {
                    uint32_t b[2] = { Bfl[nt >> 1][nt & 1], Bfl[nt >> 1][(nt & 1) + 2] };
                    mma16816h(acc[mt][nt], Af[mt], b);
                }
        }
        __syncthreads();
        if (t + 2 < NT) { load_stage(s, t + 2); CP_COMMIT(); }
    }

    const int g = lane >> 2, tig = lane & 3;
#pragma unroll
    for (int mt = 0; mt < 4; mt++) {
#pragma unroll
        for (int nt = 0; nt < 4; nt++) {
            int row0 = m0 + wm * 64 + mt * 16 + g;
            int col  = n0 + wn * 32 + nt * 8 + tig * 2;
            float2 bb = *(const float2*)(bias + col);
            float x0 = acc[mt][nt][0] + bb.x, x1 = acc[mt][nt][1] + bb.y;
            float x2 = acc[mt][nt][2] + bb.x, x3 = acc[mt][nt][3] + bb.y;
            if (Ch) {
                uint32_t h, l;
                split2h(x0, x1, h, l);
                *(uint32_t*)(Ch + (size_t)row0 * N + col) = h;
                *(uint32_t*)(Cl + (size_t)row0 * N + col) = l;
                split2h(x2, x3, h, l);
                *(uint32_t*)(Ch + (size_t)(row0 + 8) * N + col) = h;
                *(uint32_t*)(Cl + (size_t)(row0 + 8) * N + col) = l;
            } else {
                *(float2*)(C + (size_t)row0 * N + col)       = make_float2(x0, x1);
                *(float2*)(C + (size_t)(row0 + 8) * N + col) = make_float2(x2, x3);
            }
        }
    }
}

// ===========================================================================
// Flash attention via fp16 mma.sync.
// Q single fp16 (hi), K/V split hi/lo (2-pass), P single fp16.
// 1 CTA = 64 queries of one (b,h); 4 warps; 128 threads.
// ===========================================================================
#define A_KH 0
#define A_KL 8192
#define A_VH 16384
#define A_VL 24576
#define A_SMEM 32768

__global__ __launch_bounds__(128)
void attn_mma_kernel(const __half* __restrict__ qh,
                     const __half* __restrict__ ql,
                     __half* __restrict__ oh) {
    extern __shared__ char sm[];
    const uint32_t sb = smem_u32(sm);
    const int b = blockIdx.z, h = blockIdx.y, qs = blockIdx.x * 64;
    const int tid = threadIdx.x, lane = tid & 31, wid = tid >> 5;
    const int l15 = lane & 15, chi = (lane >> 4) * 16;
    const int g = lane >> 2, tig = lane & 3;
    const size_t RS = 3 * NEMBD;
    const int hcol = h * HDIM;

    // ---- stage Q (hi only) through A_KH, extract fragments ----
#pragma unroll
    for (int i = 0; i < 4; i++) {
        int idx = tid + i * 128;                   // 0..511
        int r = idx >> 3, c = idx & 7;
        const __half* src = qh + ((size_t)(b * SEQ + qs + r)) * RS + hcol + c * 8;
        *(uint4*)(sm + A_KH + swz(r, c * 16)) = *(const uint4*)src;
    }
    __syncthreads();
    uint32_t Qf[4][4];
#pragma unroll
    for (int kk = 0; kk < 4; kk++)
        ldsm4(Qf[kk], sb + A_KH + swz(wid * 16 + l15, kk * 32 + chi));
    __syncthreads();

    float o[8][4];
#pragma unroll
    for (int i = 0; i < 8; i++)
#pragma unroll
        for (int r = 0; r < 4; r++) o[i][r] = 0.f;
    float m0 = -1e30f, m1 = -1e30f, l0 = 0.f, l1 = 0.f;
    const int row0 = qs + wid * 16 + g, row1 = row0 + 8;

    int kt0 = qs - WINDOW; if (kt0 < 0) kt0 = 0;

    for (int kt = kt0; kt <= qs; kt += 64) {
        // ---- load K/V hi/lo tiles ----
#pragma unroll
        for (int i = 0; i < 16; i++) {
            int idx = tid + i * 128;
            int buf = idx >> 9;                    // 0 KH,1 KL,2 VH,3 VL
            int rem = idx & 511;
            int r = rem >> 3, c = rem & 7;
            const __half* base = ((buf & 1) == 0) ? qh : ql;
            int coff = (buf < 2) ? NEMBD : 2 * NEMBD;
            const __half* src = base
                + ((size_t)(b * SEQ + kt + r)) * RS + coff + hcol + c * 8;
            uint32_t dst = (buf == 0 ? A_KH : buf == 1 ? A_KL : buf == 2 ? A_VH : A_VL);
            *(uint4*)(sm + dst + swz(r, c * 16)) = *(const uint4*)src;
        }
        __syncthreads();

        // ---- S = Q K^T (2-pass) ----
        float s[8][4];
#pragma unroll
        for (int i = 0; i < 8; i++)
#pragma unroll
            for (int r = 0; r < 4; r++) s[i][r] = 0.f;
#pragma unroll
        for (int kk = 0; kk < 4; kk++) {
            const int cb = kk * 32 + chi;
            uint32_t Kfh[4][4], Kfl[4][4];
#pragma unroll
            for (int bt = 0; bt < 4; bt++) {
                ldsm4(Kfh[bt], sb + A_KH + swz(bt * 16 + l15, cb));
                ldsm4(Kfl[bt], sb + A_KL + swz(bt * 16 + l15, cb));
            }
#pragma unroll
            for (int nt = 0; nt < 8; nt++) {
                uint32_t bh[2] = { Kfh[nt >> 1][nt & 1], Kfh[nt >> 1][(nt & 1) + 2] };
                uint32_t bl[2] = { Kfl[nt >> 1][nt & 1], Kfl[nt >> 1][(nt & 1) + 2] };
                mma16816h(s[nt], Qf[kk], bh);
                mma16816h(s[nt], Qf[kk], bl);
            }
        }

        // ---- mask + online softmax ----
        float mx0 = -1e30f, mx1 = -1e30f;
#pragma unroll
        for (int nt = 0; nt < 8; nt++) {
            int j0 = kt + nt * 8 + tig * 2, j1 = j0 + 1;
            float v;
            v = fminf(fmaxf(s[nt][0] * ATT_SCALE, -10000.f), 10000.f);
            v = (j0 <= row0 && j0 > row0 - WINDOW) ? v : -1e30f;
            s[nt][0] = v; mx0 = fmaxf(mx0, v);
            v = fminf(fmaxf(s[nt][1] * ATT_SCALE, -10000.f), 10000.f);
            v = (j1 <= row0 && j1 > row0 - WINDOW) ? v : -1e30f;
            s[nt][1] = v; mx0 = fmaxf(mx0, v);
            v = fminf(fmaxf(s[nt][2] * ATT_SCALE, -10000.f), 10000.f);
            v = (j0 <= row1 && j0 > row1 - WINDOW) ? v : -1e30f;
            s[nt][2] = v; mx1 = fmaxf(mx1, v);
            v = fminf(fmaxf(s[nt][3] * ATT_SCALE, -10000.f), 10000.f);
            v = (j1 <= row1 && j1 > row1 - WINDOW) ? v : -1e30f;
            s[nt][3] = v; mx1 = fmaxf(mx1, v);
        }
        mx0 = qmax(mx0); mx1 = qmax(mx1);
        const float m0n = fmaxf(m0, mx0), m1n = fmaxf(m1, mx1);
        const float c0 = __expf(m0 - m0n), c1 = __expf(m1 - m1n);

        uint32_t ph01[8], ph23[8];
        float sum0 = 0.f, sum1 = 0.f;
#pragma unroll
        for (int nt = 0; nt < 8; nt++) {
            float p0 = __expf(s[nt][0] - m0n), p1 = __expf(s[nt][1] - m0n);
            float p2 = __expf(s[nt][2] - m1n), p3 = __expf(s[nt][3] - m1n);
            sum0 += p0 + p1; sum1 += p2 + p3;
            ph01[nt] = pkh2(p0, p1);
            ph23[nt] = pkh2(p2, p3);
        }
        sum0 = qsum(sum0); sum1 = qsum(sum1);
        l0 = l0 * c0 + sum0; l1 = l1 * c1 + sum1;
        m0 = m0n; m1 = m1n;
#pragma unroll
        for (int i = 0; i < 8; i++) {
            o[i][0] *= c0; o[i][1] *= c0; o[i][2] *= c1; o[i][3] *= c1;
        }

        // ---- O += P V (2-pass), V frags via ldmatrix.trans ----
#pragma unroll
        for (int kk = 0; kk < 4; kk++) {
            uint32_t pa[4] = { ph01[2 * kk], ph23[2 * kk], ph01[2 * kk + 1], ph23[2 * kk + 1] };
            uint32_t Vfh[4][4], Vfl[4][4];
#pragma unroll
            for (int db = 0; db < 4; db++) {
                ldsm4t(Vfh[db], sb + A_VH + swz(kk * 16 + l15, db * 32 + chi));
                ldsm4t(Vfl[db], sb + A_VL + swz(kk * 16 + l15, db * 32 + chi));
            }
#pragma unroll
            for (int dnt = 0; dnt < 8; dnt++) {
                uint32_t bh[2] = { Vfh[dnt >> 1][(dnt & 1) * 2], Vfh[dnt >> 1][(dnt & 1) * 2 + 1] };
                uint32_t bl[2] = { Vfl[dnt >> 1][(dnt & 1) * 2], Vfl[dnt >> 1][(dnt & 1) * 2 + 1] };
                mma16816h(o[dnt], pa, bh);
                mma16816h(o[dnt], pa, bl);
            }
        }
        __syncthreads();
    }

    // ---- epilogue: normalize, store fp16 ----
    const float i0 = 1.f / l0, i1 = 1.f / l1;
    const size_t tok0 = (size_t)(b * SEQ) + row0;
#pragma unroll
    for (int dnt = 0; dnt < 8; dnt++) {
        int col = hcol + dnt * 8 + tig * 2;
        *(uint32_t*)(oh + tok0 * NEMBD + col)       = pkh2(o[dnt][0] * i0, o[dnt][1] * i0);
        *(uint32_t*)(oh + (tok0 + 8) * NEMBD + col) = pkh2(o[dnt][2] * i1, o[dnt][3] * i1);
    }
}

// ---------------------------------------------------------------------------
extern "C" void kernel_launch(void* const* d_in, const int* in_sizes, int n_in,
                              void* d_out, int out_size) {
    const float* hidden = (const float*)d_in[0];
    const float* w_attn = (const float*)d_in[1];
    const float* b_attn = (const float*)d_in[2];
    const float* w_proj = (const float*)d_in[3];
    const float* b_proj = (const float*)d_in[4];
    float* out = (float*)d_out;

    __half *kvh, *kvl, *ah, *wh, *wl, *ph, *pl, *oh;
    cudaGetSymbolAddress((void**)&kvh, g_kvh); cudaGetSymbolAddress((void**)&kvl, g_kvl);
    cudaGetSymbolAddress((void**)&ah, g_ah);
    cudaGetSymbolAddress((void**)&wh, g_wh); cudaGetSymbolAddress((void**)&wl, g_wl);
    cudaGetSymbolAddress((void**)&ph, g_ph); cudaGetSymbolAddress((void**)&pl, g_pl);
    cudaGetSymbolAddress((void**)&oh, g_oh);

    const int M = BATCH * SEQ;       // 4096
    const int E = NEMBD;             // 1024

    cudaFuncSetAttribute(gemm_h_kernel,
                         cudaFuncAttributeMaxDynamicSharedMemorySize, GSMEM);
    cudaFuncSetAttribute(attn_mma_kernel,
                         cudaFuncAttributeMaxDynamicSharedMemorySize, A_SMEM);

    // 0) conversions
    {
        int n4 = M * E / 4;
        cvt_h_kernel<<<(n4 + 255) / 256, 256>>>(hidden, ah, n4);
    }
    split_tr_h_kernel<<<dim3(3 * E / 32, E / 32), dim3(32, 8)>>>(w_attn, wh, wl, E, 3 * E);
    split_tr_h_kernel<<<dim3(E / 32, E / 32), dim3(32, 8)>>>(w_proj, ph, pl, E, E);

    // 1) QKV projection -> split fp16 qkv
    gemm_h_kernel<<<dim3(3 * E / 128, M / 128), 256, GSMEM>>>(
        ah, wh, wl, b_attn, nullptr, kvh, kvl, M, 3 * E, E);
    // 2) flash attention -> fp16
    attn_mma_kernel<<<dim3(SEQ / 64, NHEAD, BATCH), 128, A_SMEM>>>(kvh, kvl, oh);
    // 3) output projection -> fp32
    gemm_h_kernel<<<dim3(E / 128, M / 128), 256, GSMEM>>>(
        oh, ph, pl, b_proj, out, nullptr, nullptr, M, E, E);
}

// round 10
// speedup vs baseline: 1.5319x; 1.0254x over previous
#include <cuda_runtime.h>
#include <cuda_fp16.h>
#include <cstdint>

#define BATCH 2
#define SEQ 2048
#define NEMBD 1024
#define NHEAD 16
#define HDIM 64
#define WINDOW 256
#define ATT_SCALE 0.125f   // 1/sqrt(64)

// ---------------- device scratch (allocation-free rule) ----------------
__device__ __half g_kvh[(size_t)4096 * 3072];      // qkv hi (fp16)
__device__ __half g_kvl[(size_t)4096 * 3072];      // qkv lo
__device__ __half g_ah[(size_t)4096 * 1024];       // hidden fp16 (single)
__device__ __half g_wh[(size_t)3072 * 1024];       // w_attn^T hi [N][K]
__device__ __half g_wl[(size_t)3072 * 1024];
__device__ __half g_ph[(size_t)1024 * 1024];       // w_proj^T hi
__device__ __half g_pl[(size_t)1024 * 1024];
__device__ __half g_oh[(size_t)4096 * 1024];       // attn out fp16 (single)

// ---------------- helpers ----------------
__device__ __forceinline__ uint32_t smem_u32(const void* p) {
    uint32_t a;
    asm("{ .reg .u64 t; cvta.to.shared.u64 t, %1; cvt.u32.u64 %0, t; }"
        : "=r"(a) : "l"(p));
    return a;
}
__device__ __forceinline__ void split2h(float a, float b, uint32_t& hi, uint32_t& lo) {
    __half2 h = __floats2half2_rn(a, b);
    float ra = a - __half2float(__low2half(h));
    float rb = b - __half2float(__high2half(h));
    __half2 L = __floats2half2_rn(ra, rb);
    hi = *(uint32_t*)&h; lo = *(uint32_t*)&L;
}
__device__ __forceinline__ uint32_t pkh2(float a, float b) {
    __half2 h = __floats2half2_rn(a, b);
    return *(uint32_t*)&h;
}
__device__ __forceinline__ void mma16816h(float* c, const uint32_t* a, const uint32_t* b) {
    asm volatile(
        "mma.sync.aligned.m16n8k16.row.col.f32.f16.f16.f32 "
        "{%0,%1,%2,%3},{%4,%5,%6,%7},{%8,%9},{%0,%1,%2,%3};"
        : "+f"(c[0]), "+f"(c[1]), "+f"(c[2]), "+f"(c[3])
        : "r"(a[0]), "r"(a[1]), "r"(a[2]), "r"(a[3]), "r"(b[0]), "r"(b[1]));
}
__device__ __forceinline__ void ldsm4(uint32_t* r, uint32_t addr) {
    asm volatile("ldmatrix.sync.aligned.m8n8.x4.shared.b16 {%0,%1,%2,%3}, [%4];"
                 : "=r"(r[0]), "=r"(r[1]), "=r"(r[2]), "=r"(r[3]) : "r"(addr));
}
__device__ __forceinline__ void ldsm4t(uint32_t* r, uint32_t addr) {
    asm volatile("ldmatrix.sync.aligned.m8n8.x4.trans.shared.b16 {%0,%1,%2,%3}, [%4];"
                 : "=r"(r[0]), "=r"(r[1]), "=r"(r[2]), "=r"(r[3]) : "r"(addr));
}
__device__ __forceinline__ void cpa16(uint32_t saddr, const void* gaddr) {
    asm volatile("cp.async.cg.shared.global [%0], [%1], 16;" :: "r"(saddr), "l"(gaddr));
}
#define CP_COMMIT() asm volatile("cp.async.commit_group;")
#define CP_WAIT0()  asm volatile("cp.async.wait_group 0;")
#define CP_WAIT1()  asm volatile("cp.async.wait_group 1;")

// SW128 swizzle for 128B rows
__device__ __forceinline__ uint32_t swz(int row, int col) {
    return (uint32_t)(row * 128 + (col ^ ((row & 7) << 4)));
}
__device__ __forceinline__ float qmax(float v) {
    v = fmaxf(v, __shfl_xor_sync(0xFFFFFFFFu, v, 1));
    v = fmaxf(v, __shfl_xor_sync(0xFFFFFFFFu, v, 2));
    return v;
}
__device__ __forceinline__ float qsum(float v) {
    v += __shfl_xor_sync(0xFFFFFFFFu, v, 1);
    v += __shfl_xor_sync(0xFFFFFFFFu, v, 2);
    return v;
}

// ===========================================================================
// conversion kernels
// ===========================================================================
__global__ void cvt_h_kernel(const float* __restrict__ src,
                             __half* __restrict__ dst, int n4) {
    int i = blockIdx.x * blockDim.x + threadIdx.x;
    if (i < n4) {
        float4 v = *(const float4*)(src + (size_t)i * 4);
        __half2 h01 = __floats2half2_rn(v.x, v.y);
        __half2 h23 = __floats2half2_rn(v.z, v.w);
        uint2 o; o.x = *(uint32_t*)&h01; o.y = *(uint32_t*)&h23;
        *(uint2*)(dst + (size_t)i * 4) = o;
    }
}
// src [K,N] fp32 row-major -> dst [N][K] fp16 hi/lo
__global__ void split_tr_h_kernel(const float* __restrict__ src,
                                  __half* __restrict__ hi,
                                  __half* __restrict__ lo, int K, int N) {
    __shared__ float t[32][33];
    const int n0 = blockIdx.x * 32, k0 = blockIdx.y * 32;
    const int tx = threadIdx.x, ty = threadIdx.y;   // 32 x 8
#pragma unroll
    for (int i = 0; i < 4; i++)
        t[ty + i * 8][tx] = src[(size_t)(k0 + ty + i * 8) * N + n0 + tx];
    __syncthreads();
#pragma unroll
    for (int i = 0; i < 4; i++) {
        int n = ty + i * 8;
        float v = t[tx][n];
        __half h = __float2half_rn(v);
        float l = v - __half2float(h);
        hi[(size_t)(n0 + n) * K + k0 + tx] = h;
        lo[(size_t)(n0 + n) * K + k0 + tx] = __float2half_rn(l);
    }
}

// ===========================================================================
// 2-pass fp16 GEMM with register fragment double-buffering.
// A single fp16, B split hi/lo. CTA 128x128, BK=64, 2-stage cp.async, SW128.
// ===========================================================================
#define ST_A  0
#define ST_BH 16384
#define ST_BL 32768
#define ST_SZ 49152
#define GSMEM (2 * ST_SZ)

__global__ __launch_bounds__(256, 1)
void gemm_h_kernel(const __half* __restrict__ A,
                   const __half* __restrict__ Bh, const __half* __restrict__ Bl,
                   const float* __restrict__ bias, float* __restrict__ C,
                   __half* __restrict__ Ch, __half* __restrict__ Cl,
                   int M, int N, int K) {
    extern __shared__ char sm[];
    const uint32_t sb = smem_u32(sm);
    const int tid = threadIdx.x, lane = tid & 31, wid = tid >> 5;
    const int m0 = blockIdx.y * 128, n0 = blockIdx.x * 128;
    const int wm = wid >> 2, wn = wid & 3;          // 2 x 4 warp grid, tile 64x32
    const int l15 = lane & 15, chi = (lane >> 4) * 16;
    const int lrow = tid >> 3, lc = tid & 7;
    const int NT = K / 64;

    float acc[4][4][4];
#pragma unroll
    for (int i = 0; i < 4; i++)
#pragma unroll
        for (int j = 0; j < 4; j++)
#pragma unroll
            for (int r = 0; r < 4; r++) acc[i][j][r] = 0.f;

    auto load_stage = [&](int s, int kt) {
        const uint32_t sbase = sb + s * ST_SZ;
        const size_t gk = (size_t)kt * 64 + lc * 8;
#pragma unroll
        for (int i = 0; i < 4; i++) {
            const int row = lrow + i * 32;
            const uint32_t so = swz(row, lc * 16);
            cpa16(sbase + ST_A  + so, A  + (size_t)(m0 + row) * K + gk);
            cpa16(sbase + ST_BH + so, Bh + (size_t)(n0 + row) * K + gk);
            cpa16(sbase + ST_BL + so, Bl + (size_t)(n0 + row) * K + gk);
        }
    };

    // double-buffered fragments
    uint32_t Af[2][4][4], Bfh[2][2][4], Bfl[2][2][4];

    auto load_frags = [&](int fb, uint32_t abase, int ks) {
        const int cb = ks * 32 + chi;
#pragma unroll
        for (int mt = 0; mt < 4; mt++)
            ldsm4(Af[fb][mt], abase + ST_A + swz(wm * 64 + mt * 16 + l15, cb));
#pragma unroll
        for (int bt = 0; bt < 2; bt++) {
            ldsm4(Bfh[fb][bt], abase + ST_BH + swz(wn * 32 + bt * 16 + l15, cb));
            ldsm4(Bfl[fb][bt], abase + ST_BL + swz(wn * 32 + bt * 16 + l15, cb));
        }
    };

    load_stage(0, 0); CP_COMMIT();
    load_stage(1, 1); CP_COMMIT();

    for (int t = 0; t < NT; t++) {
        const int s = t & 1;
        CP_WAIT1();
        __syncthreads();

        const uint32_t abase = sb + s * ST_SZ;
        load_frags(0, abase, 0);
#pragma unroll
        for (int ks = 0; ks < 4; ks++) {
            const int cur = ks & 1;
            if (ks < 3) load_frags(cur ^ 1, abase, ks + 1);
            // pass 1: A * Bh
#pragma unroll
            for (int mt = 0; mt < 4; mt++)
#pragma unroll
                for (int nt = 0; nt < 4; nt++) {
                    uint32_t b[2] = { Bfh[cur][nt >> 1][nt & 1], Bfh[cur][nt >> 1][(nt & 1) + 2] };
                    mma16816h(acc[mt][nt], Af[cur][mt], b);
                }
            // pass 2: A * Bl
#pragma unroll
            for (int mt = 0; mt < 4; mt++)
#pragma unroll
                for (int nt = 0; nt < 4; nt++) {
                    uint32_t b[2] = { Bfl[cur][nt >> 1][nt & 1], Bfl[cur][nt >> 1][(nt & 1) + 2] };
                    mma16816h(acc[mt][nt], Af[cur][mt], b);
                }
        }
        __syncthreads();
        if (t + 2 < NT) { load_stage(s, t + 2); CP_COMMIT(); }
    }

    const int g = lane >> 2, tig = lane & 3;
#pragma unroll
    for (int mt = 0; mt < 4; mt++) {
#pragma unroll
        for (int nt = 0; nt < 4; nt++) {
            int row0 = m0 + wm * 64 + mt * 16 + g;
            int col  = n0 + wn * 32 + nt * 8 + tig * 2;
            float2 bb = *(const float2*)(bias + col);
            float x0 = acc[mt][nt][0] + bb.x, x1 = acc[mt][nt][1] + bb.y;
            float x2 = acc[mt][nt][2] + bb.x, x3 = acc[mt][nt][3] + bb.y;
            if (Ch) {
                uint32_t h, l;
                split2h(x0, x1, h, l);
                *(uint32_t*)(Ch + (size_t)row0 * N + col) = h;
                *(uint32_t*)(Cl + (size_t)row0 * N + col) = l;
                split2h(x2, x3, h, l);
                *(uint32_t*)(Ch + (size_t)(row0 + 8) * N + col) = h;
                *(uint32_t*)(Cl + (size_t)(row0 + 8) * N + col) = l;
            } else {
                *(float2*)(C + (size_t)row0 * N + col)       = make_float2(x0, x1);
                *(float2*)(C + (size_t)(row0 + 8) * N + col) = make_float2(x2, x3);
            }
        }
    }
}

// ===========================================================================
// Flash attention, fp16 mma.sync, cp.async double-buffered K/V tiles.
// Q single fp16, K/V split hi/lo (2-pass), P single fp16.
// ===========================================================================
#define AQ_OFF  0                              // Q staging: 8KB
#define AS_OFF  8192                           // stage s at 8192 + s*32768
#define AS_SZ   32768                          // KH,KL,VH,VL (8KB each)
#define A_SMEM  (8192 + 2 * 32768)             // 73728

__global__ __launch_bounds__(128)
void attn_mma_kernel(const __half* __restrict__ qh,
                     const __half* __restrict__ ql,
                     __half* __restrict__ oh) {
    extern __shared__ char sm[];
    const uint32_t sb = smem_u32(sm);
    const int b = blockIdx.z, h = blockIdx.y, qs = blockIdx.x * 64;
    const int tid = threadIdx.x, lane = tid & 31, wid = tid >> 5;
    const int l15 = lane & 15, chi = (lane >> 4) * 16;
    const int g = lane >> 2, tig = lane & 3;
    const size_t RS = 3 * NEMBD;
    const int hcol = h * HDIM;

    const int kt0 = (qs - WINDOW < 0) ? 0 : qs - WINDOW;
    const int ntiles = (qs - kt0) / 64 + 1;

    // K/V tile async load into stage s (buf: 0 KH, 1 KL, 2 VH, 3 VL)
    auto load_kv = [&](int s, int kt) {
        const uint32_t sbase = sb + AS_OFF + s * AS_SZ;
#pragma unroll
        for (int i = 0; i < 16; i++) {
            int idx = tid + i * 128;
            int buf = idx >> 9;
            int rem = idx & 511;
            int r = rem >> 3, c = rem & 7;
            const __half* base = ((buf & 1) == 0) ? qh : ql;
            int coff = (buf < 2) ? NEMBD : 2 * NEMBD;
            const __half* src = base
                + ((size_t)(b * SEQ + kt + r)) * RS + coff + hcol + c * 8;
            cpa16(sbase + buf * 8192 + swz(r, c * 16), src);
        }
    };

    // issue first K/V load, then stage Q while it flies
    load_kv(0, kt0); CP_COMMIT();
#pragma unroll
    for (int i = 0; i < 4; i++) {
        int idx = tid + i * 128;                   // 0..511
        int r = idx >> 3, c = idx & 7;
        const __half* src = qh + ((size_t)(b * SEQ + qs + r)) * RS + hcol + c * 8;
        *(uint4*)(sm + AQ_OFF + swz(r, c * 16)) = *(const uint4*)src;
    }
    __syncthreads();
    uint32_t Qf[4][4];
#pragma unroll
    for (int kk = 0; kk < 4; kk++)
        ldsm4(Qf[kk], sb + AQ_OFF + swz(wid * 16 + l15, kk * 32 + chi));

    float o[8][4];
#pragma unroll
    for (int i = 0; i < 8; i++)
#pragma unroll
        for (int r = 0; r < 4; r++) o[i][r] = 0.f;
    float m0 = -1e30f, m1 = -1e30f, l0 = 0.f, l1 = 0.f;
    const int row0 = qs + wid * 16 + g, row1 = row0 + 8;

    for (int it = 0; it < ntiles; it++) {
        const int kt = kt0 + it * 64;
        const int cur = it & 1;
        const bool pf = (it + 1 < ntiles);
        if (pf) { load_kv(cur ^ 1, kt + 64); CP_COMMIT(); }
        if (pf) { CP_WAIT1(); } else { CP_WAIT0(); }
        __syncthreads();

        const uint32_t kbase = sb + AS_OFF + cur * AS_SZ;

        // ---- S = Q K^T (2-pass) ----
        float s[8][4];
#pragma unroll
        for (int i = 0; i < 8; i++)
#pragma unroll
            for (int r = 0; r < 4; r++) s[i][r] = 0.f;
#pragma unroll
        for (int kk = 0; kk < 4; kk++) {
            const int cb = kk * 32 + chi;
            uint32_t Kfh[4][4], Kfl[4][4];
#pragma unroll
            for (int bt = 0; bt < 4; bt++) {
                ldsm4(Kfh[bt], kbase + swz(bt * 16 + l15, cb));            // KH
                ldsm4(Kfl[bt], kbase + 8192 + swz(bt * 16 + l15, cb));     // KL
            }
#pragma unroll
            for (int nt = 0; nt < 8; nt++) {
                uint32_t bh[2] = { Kfh[nt >> 1][nt & 1], Kfh[nt >> 1][(nt & 1) + 2] };
                uint32_t bl[2] = { Kfl[nt >> 1][nt & 1], Kfl[nt >> 1][(nt & 1) + 2] };
                mma16816h(s[nt], Qf[kk], bh);
                mma16816h(s[nt], Qf[kk], bl);
            }
        }

        // ---- mask + online softmax ----
        float mx0 = -1e30f, mx1 = -1e30f;
#pragma unroll
        for (int nt = 0; nt < 8; nt++) {
            int j0 = kt + nt * 8 + tig * 2, j1 = j0 + 1;
            float v;
            v = fminf(fmaxf(s[nt][0] * ATT_SCALE, -10000.f), 10000.f);
            v = (j0 <= row0 && j0 > row0 - WINDOW) ? v : -1e30f;
            s[nt][0] = v; mx0 = fmaxf(mx0, v);
            v = fminf(fmaxf(s[nt][1] * ATT_SCALE, -10000.f), 10000.f);
            v = (j1 <= row0 && j1 > row0 - WINDOW) ? v : -1e30f;
            s[nt][1] = v; mx0 = fmaxf(mx0, v);
            v = fminf(fmaxf(s[nt][2] * ATT_SCALE, -10000.f), 10000.f);
            v = (j0 <= row1 && j0 > row1 - WINDOW) ? v : -1e30f;
            s[nt][2] = v; mx1 = fmaxf(mx1, v);
            v = fminf(fmaxf(s[nt][3] * ATT_SCALE, -10000.f), 10000.f);
            v = (j1 <= row1 && j1 > row1 - WINDOW) ? v : -1e30f;
            s[nt][3] = v; mx1 = fmaxf(mx1, v);
        }
        mx0 = qmax(mx0); mx1 = qmax(mx1);
        const float m0n = fmaxf(m0, mx0), m1n = fmaxf(m1, mx1);
        const float c0 = __expf(m0 - m0n), c1 = __expf(m1 - m1n);

        uint32_t ph01[8], ph23[8];
        float sum0 = 0.f, sum1 = 0.f;
#pragma unroll
        for (int nt = 0; nt < 8; nt++) {
            float p0 = __expf(s[nt][0] - m0n), p1 = __expf(s[nt][1] - m0n);
            float p2 = __expf(s[nt][2] - m1n), p3 = __expf(s[nt][3] - m1n);
            sum0 += p0 + p1; sum1 += p2 + p3;
            ph01[nt] = pkh2(p0, p1);
            ph23[nt] = pkh2(p2, p3);
        }
        sum0 = qsum(sum0); sum1 = qsum(sum1);
        l0 = l0 * c0 + sum0; l1 = l1 * c1 + sum1;
        m0 = m0n; m1 = m1n;
#pragma unroll
        for (int i = 0; i < 8; i++) {
            o[i][0] *= c0; o[i][1] *= c0; o[i][2] *= c1; o[i][3] *= c1;
        }

        // ---- O += P V (2-pass), V frags via ldmatrix.trans ----
#pragma unroll
        for (int kk = 0; kk < 4; kk++) {
            uint32_t pa[4] = { ph01[2 * kk], ph23[2 * kk], ph01[2 * kk + 1], ph23[2 * kk + 1] };
            uint32_t Vfh[4][4], Vfl[4][4];
#pragma unroll
            for (int db = 0; db < 4; db++) {
                ldsm4t(Vfh[db], kbase + 16384 + swz(kk * 16 + l15, db * 32 + chi));  // VH
                ldsm4t(Vfl[db], kbase + 24576 + swz(kk * 16 + l15, db * 32 + chi));  // VL
            }
#pragma unroll
            for (int dnt = 0; dnt < 8; dnt++) {
                uint32_t bh[2] = { Vfh[dnt >> 1][(dnt & 1) * 2], Vfh[dnt >> 1][(dnt & 1) * 2 + 1] };
                uint32_t bl[2] = { Vfl[dnt >> 1][(dnt & 1) * 2], Vfl[dnt >> 1][(dnt & 1) * 2 + 1] };
                mma16816h(o[dnt], pa, bh);
                mma16816h(o[dnt], pa, bl);
            }
        }
        __syncthreads();   // all warps done reading stage `cur` before it is refilled
    }

    // ---- epilogue: normalize, store fp16 ----
    const float i0 = 1.f / l0, i1 = 1.f / l1;
    const size_t tok0 = (size_t)(b * SEQ) + row0;
#pragma unroll
    for (int dnt = 0; dnt < 8; dnt++) {
        int col = hcol + dnt * 8 + tig * 2;
        *(uint32_t*)(oh + tok0 * NEMBD + col)       = pkh2(o[dnt][0] * i0, o[dnt][1] * i0);
        *(uint32_t*)(oh + (tok0 + 8) * NEMBD + col) = pkh2(o[dnt][2] * i1, o[dnt][3] * i1);
    }
}

// ---------------------------------------------------------------------------
extern "C" void kernel_launch(void* const* d_in, const int* in_sizes, int n_in,
                              void* d_out, int out_size) {
    const float* hidden = (const float*)d_in[0];
    const float* w_attn = (const float*)d_in[1];
    const float* b_attn = (const float*)d_in[2];
    const float* w_proj = (const float*)d_in[3];
    const float* b_proj = (const float*)d_in[4];
    float* out = (float*)d_out;

    __half *kvh, *kvl, *ah, *wh, *wl, *ph, *pl, *oh;
    cudaGetSymbolAddress((void**)&kvh, g_kvh); cudaGetSymbolAddress((void**)&kvl, g_kvl);
    cudaGetSymbolAddress((void**)&ah, g_ah);
    cudaGetSymbolAddress((void**)&wh, g_wh); cudaGetSymbolAddress((void**)&wl, g_wl);
    cudaGetSymbolAddress((void**)&ph, g_ph); cudaGetSymbolAddress((void**)&pl, g_pl);
    cudaGetSymbolAddress((void**)&oh, g_oh);

    const int M = BATCH * SEQ;       // 4096
    const int E = NEMBD;             // 1024

    cudaFuncSetAttribute(gemm_h_kernel,
                         cudaFuncAttributeMaxDynamicSharedMemorySize, GSMEM);
    cudaFuncSetAttribute(attn_mma_kernel,
                         cudaFuncAttributeMaxDynamicSharedMemorySize, A_SMEM);

    // 0) conversions
    {
        int n4 = M * E / 4;
        cvt_h_kernel<<<(n4 + 255) / 256, 256>>>(hidden, ah, n4);
    }
    split_tr_h_kernel<<<dim3(3 * E / 32, E / 32), dim3(32, 8)>>>(w_attn, wh, wl, E, 3 * E);
    split_tr_h_kernel<<<dim3(E / 32, E / 32), dim3(32, 8)>>>(w_proj, ph, pl, E, E);

    // 1) QKV projection -> split fp16 qkv
    gemm_h_kernel<<<dim3(3 * E / 128, M / 128), 256, GSMEM>>>(
        ah, wh, wl, b_attn, nullptr, kvh, kvl, M, 3 * E, E);
    // 2) flash attention -> fp16
    attn_mma_kernel<<<dim3(SEQ / 64, NHEAD, BATCH), 128, A_SMEM>>>(kvh, kvl, oh);
    // 3) output projection -> fp32
    gemm_h_kernel<<<dim3(E / 128, M / 128), 256, GSMEM>>>(
        oh, ph, pl, b_proj, out, nullptr, nullptr, M, E, E);
}

// round 11
// speedup vs baseline: 2.4622x; 1.6073x over previous
#include <cuda_runtime.h>
#include <cuda_fp16.h>
#include <cstdint>

#define BATCH 2
#define SEQ 2048
#define NEMBD 1024
#define NHEAD 16
#define HDIM 64
#define WINDOW 256
#define ATT_SCALE 0.125f   // 1/sqrt(64)

// ---------------- device scratch (allocation-free rule) ----------------
__device__ __half g_kvh[(size_t)4096 * 3072];      // qkv fp16
__device__ __half g_ah[(size_t)4096 * 1024];       // hidden fp16
__device__ __half g_wh[(size_t)3072 * 1024];       // w_attn^T fp16 [N][K]
__device__ __half g_ph[(size_t)1024 * 1024];       // w_proj^T fp16
__device__ __half g_oh[(size_t)4096 * 1024];       // attn out fp16

// ---------------- helpers ----------------
__device__ __forceinline__ uint32_t smem_u32(const void* p) {
    uint32_t a;
    asm("{ .reg .u64 t; cvta.to.shared.u64 t, %1; cvt.u32.u64 %0, t; }"
        : "=r"(a) : "l"(p));
    return a;
}
__device__ __forceinline__ uint32_t pkh2(float a, float b) {
    __half2 h = __floats2half2_rn(a, b);
    return *(uint32_t*)&h;
}
__device__ __forceinline__ void mma16816h(float* c, const uint32_t* a, const uint32_t* b) {
    asm volatile(
        "mma.sync.aligned.m16n8k16.row.col.f32.f16.f16.f32 "
        "{%0,%1,%2,%3},{%4,%5,%6,%7},{%8,%9},{%0,%1,%2,%3};"
        : "+f"(c[0]), "+f"(c[1]), "+f"(c[2]), "+f"(c[3])
        : "r"(a[0]), "r"(a[1]), "r"(a[2]), "r"(a[3]), "r"(b[0]), "r"(b[1]));
}
__device__ __forceinline__ void ldsm4(uint32_t* r, uint32_t addr) {
    asm volatile("ldmatrix.sync.aligned.m8n8.x4.shared.b16 {%0,%1,%2,%3}, [%4];"
                 : "=r"(r[0]), "=r"(r[1]), "=r"(r[2]), "=r"(r[3]) : "r"(addr));
}
__device__ __forceinline__ void ldsm4t(uint32_t* r, uint32_t addr) {
    asm volatile("ldmatrix.sync.aligned.m8n8.x4.trans.shared.b16 {%0,%1,%2,%3}, [%4];"
                 : "=r"(r[0]), "=r"(r[1]), "=r"(r[2]), "=r"(r[3]) : "r"(addr));
}
__device__ __forceinline__ void cpa16(uint32_t saddr, const void* gaddr) {
    asm volatile("cp.async.cg.shared.global [%0], [%1], 16;" :: "r"(saddr), "l"(gaddr));
}
#define CP_COMMIT() asm volatile("cp.async.commit_group;")
#define CP_WAIT0()  asm volatile("cp.async.wait_group 0;")
#define CP_WAIT1()  asm volatile("cp.async.wait_group 1;")

// SW128 swizzle for 128B rows
__device__ __forceinline__ uint32_t swz(int row, int col) {
    return (uint32_t)(row * 128 + (col ^ ((row & 7) << 4)));
}
__device__ __forceinline__ float qmax(float v) {
    v = fmaxf(v, __shfl_xor_sync(0xFFFFFFFFu, v, 1));
    v = fmaxf(v, __shfl_xor_sync(0xFFFFFFFFu, v, 2));
    return v;
}
__device__ __forceinline__ float qsum(float v) {
    v += __shfl_xor_sync(0xFFFFFFFFu, v, 1);
    v += __shfl_xor_sync(0xFFFFFFFFu, v, 2);
    return v;
}

// ===========================================================================
// conversion kernels
// ===========================================================================
__global__ void cvt_h_kernel(const float* __restrict__ src,
                             __half* __restrict__ dst, int n4) {
    int i = blockIdx.x * blockDim.x + threadIdx.x;
    if (i < n4) {
        float4 v = *(const float4*)(src + (size_t)i * 4);
        uint2 o;
        o.x = pkh2(v.x, v.y);
        o.y = pkh2(v.z, v.w);
        *(uint2*)(dst + (size_t)i * 4) = o;
    }
}
// src [K,N] fp32 row-major -> dst [N][K] fp16
__global__ void cvt_tr_h_kernel(const float* __restrict__ src,
                                __half* __restrict__ dst, int K, int N) {
    __shared__ float t[32][33];
    const int n0 = blockIdx.x * 32, k0 = blockIdx.y * 32;
    const int tx = threadIdx.x, ty = threadIdx.y;   // 32 x 8
#pragma unroll
    for (int i = 0; i < 4; i++)
        t[ty + i * 8][tx] = src[(size_t)(k0 + ty + i * 8) * N + n0 + tx];
    __syncthreads();
#pragma unroll
    for (int i = 0; i < 4; i++) {
        int n = ty + i * 8;
        dst[(size_t)(n0 + n) * K + k0 + tx] = __float2half_rn(t[tx][n]);
    }
}

// ===========================================================================
// single-pass fp16 GEMM: C[M,N] = A[M,K] @ B[N,K]^T + bias
// CTA 128x128, BK=64, 2-stage cp.async, SW128, 256 threads, warp tile 64x32.
// If Ch != null, writes fp16 C instead of fp32.
// ===========================================================================
#define ST_A  0
#define ST_B  16384
#define ST_SZ 32768
#define GSMEM (2 * ST_SZ)

__global__ __launch_bounds__(256, 1)
void gemm_h_kernel(const __half* __restrict__ A, const __half* __restrict__ B,
                   const float* __restrict__ bias, float* __restrict__ C,
                   __half* __restrict__ Ch,
                   int M, int N, int K) {
    extern __shared__ char sm[];
    const uint32_t sb = smem_u32(sm);
    const int tid = threadIdx.x, lane = tid & 31, wid = tid >> 5;
    const int m0 = blockIdx.y * 128, n0 = blockIdx.x * 128;
    const int wm = wid >> 2, wn = wid & 3;          // 2 x 4 warp grid, tile 64x32
    const int l15 = lane & 15, chi = (lane >> 4) * 16;
    const int lrow = tid >> 3, lc = tid & 7;
    const int NT = K / 64;

    float acc[4][4][4];
#pragma unroll
    for (int i = 0; i < 4; i++)
#pragma unroll
        for (int j = 0; j < 4; j++)
#pragma unroll
            for (int r = 0; r < 4; r++) acc[i][j][r] = 0.f;

    auto load_stage = [&](int s, int kt) {
        const uint32_t sbase = sb + s * ST_SZ;
        const size_t gk = (size_t)kt * 64 + lc * 8;
#pragma unroll
        for (int i = 0; i < 4; i++) {
            const int row = lrow + i * 32;
            const uint32_t so = swz(row, lc * 16);
            cpa16(sbase + ST_A + so, A + (size_t)(m0 + row) * K + gk);
            cpa16(sbase + ST_B + so, B + (size_t)(n0 + row) * K + gk);
        }
    };

    // register double-buffered fragments
    uint32_t Af[2][4][4], Bf[2][2][4];
    auto load_frags = [&](int fb, uint32_t abase, int ks) {
        const int cb = ks * 32 + chi;
#pragma unroll
        for (int mt = 0; mt < 4; mt++)
            ldsm4(Af[fb][mt], abase + ST_A + swz(wm * 64 + mt * 16 + l15, cb));
#pragma unroll
        for (int bt = 0; bt < 2; bt++)
            ldsm4(Bf[fb][bt], abase + ST_B + swz(wn * 32 + bt * 16 + l15, cb));
    };

    load_stage(0, 0); CP_COMMIT();
    load_stage(1, 1); CP_COMMIT();

    for (int t = 0; t < NT; t++) {
        const int s = t & 1;
        CP_WAIT1();
        __syncthreads();

        const uint32_t abase = sb + s * ST_SZ;
        load_frags(0, abase, 0);
#pragma unroll
        for (int ks = 0; ks < 4; ks++) {
            const int cur = ks & 1;
            if (ks < 3) load_frags(cur ^ 1, abase, ks + 1);
#pragma unroll
            for (int mt = 0; mt < 4; mt++)
#pragma unroll
                for (int nt = 0; nt < 4; nt++) {
                    uint32_t b[2] = { Bf[cur][nt >> 1][nt & 1], Bf[cur][nt >> 1][(nt & 1) + 2] };
                    mma16816h(acc[mt][nt], Af[cur][mt], b);
                }
        }
        __syncthreads();
        if (t + 2 < NT) { load_stage(s, t + 2); CP_COMMIT(); }
    }

    const int g = lane >> 2, tig = lane & 3;
#pragma unroll
    for (int mt = 0; mt < 4; mt++) {
#pragma unroll
        for (int nt = 0; nt < 4; nt++) {
            int row0 = m0 + wm * 64 + mt * 16 + g;
            int col  = n0 + wn * 32 + nt * 8 + tig * 2;
            float2 bb = *(const float2*)(bias + col);
            float x0 = acc[mt][nt][0] + bb.x, x1 = acc[mt][nt][1] + bb.y;
            float x2 = acc[mt][nt][2] + bb.x, x3 = acc[mt][nt][3] + bb.y;
            if (Ch) {
                *(uint32_t*)(Ch + (size_t)row0 * N + col)       = pkh2(x0, x1);
                *(uint32_t*)(Ch + (size_t)(row0 + 8) * N + col) = pkh2(x2, x3);
            } else {
                *(float2*)(C + (size_t)row0 * N + col)       = make_float2(x0, x1);
                *(float2*)(C + (size_t)(row0 + 8) * N + col) = make_float2(x2, x3);
            }
        }
    }
}

// ===========================================================================
// Flash attention, single-pass fp16 mma.sync, cp.async double-buffered K/V.
// 1 CTA = 64 queries of one (b,h); 4 warps; 128 threads.
// ===========================================================================
#define AQ_OFF  0                              // Q staging: 8KB
#define AS_OFF  8192                           // stage s at 8192 + s*16384
#define AS_SZ   16384                          // K (8KB) + V (8KB)
#define A_SMEM  (8192 + 2 * 16384)             // 40960

__global__ __launch_bounds__(128)
void attn_mma_kernel(const __half* __restrict__ qkv, __half* __restrict__ oh) {
    extern __shared__ char sm[];
    const uint32_t sb = smem_u32(sm);
    const int b = blockIdx.z, h = blockIdx.y, qs = blockIdx.x * 64;
    const int tid = threadIdx.x, lane = tid & 31, wid = tid >> 5;
    const int l15 = lane & 15, chi = (lane >> 4) * 16;
    const int g = lane >> 2, tig = lane & 3;
    const size_t RS = 3 * NEMBD;
    const int hcol = h * HDIM;

    const int kt0 = (qs - WINDOW < 0) ? 0 : qs - WINDOW;
    const int ntiles = (qs - kt0) / 64 + 1;

    // K/V tile async load into stage s (buf: 0 K, 1 V)
    auto load_kv = [&](int s, int kt) {
        const uint32_t sbase = sb + AS_OFF + s * AS_SZ;
#pragma unroll
        for (int i = 0; i < 8; i++) {
            int idx = tid + i * 128;               // 0..1023
            int buf = idx >> 9;                    // 0 K, 1 V
            int rem = idx & 511;
            int r = rem >> 3, c = rem & 7;
            const __half* src = qkv
                + ((size_t)(b * SEQ + kt + r)) * RS + NEMBD + buf * NEMBD + hcol + c * 8;
            cpa16(sbase + buf * 8192 + swz(r, c * 16), src);
        }
    };

    load_kv(0, kt0); CP_COMMIT();
    // stage Q while K/V flies
#pragma unroll
    for (int i = 0; i < 4; i++) {
        int idx = tid + i * 128;                   // 0..511
        int r = idx >> 3, c = idx & 7;
        const __half* src = qkv + ((size_t)(b * SEQ + qs + r)) * RS + hcol + c * 8;
        *(uint4*)(sm + AQ_OFF + swz(r, c * 16)) = *(const uint4*)src;
    }
    __syncthreads();
    uint32_t Qf[4][4];
#pragma unroll
    for (int kk = 0; kk < 4; kk++)
        ldsm4(Qf[kk], sb + AQ_OFF + swz(wid * 16 + l15, kk * 32 + chi));

    float o[8][4];
#pragma unroll
    for (int i = 0; i < 8; i++)
#pragma unroll
        for (int r = 0; r < 4; r++) o[i][r] = 0.f;
    float m0 = -1e30f, m1 = -1e30f, l0 = 0.f, l1 = 0.f;
    const int row0 = qs + wid * 16 + g, row1 = row0 + 8;

    for (int it = 0; it < ntiles; it++) {
        const int kt = kt0 + it * 64;
        const int cur = it & 1;
        const bool pf = (it + 1 < ntiles);
        if (pf) { load_kv(cur ^ 1, kt + 64); CP_COMMIT(); }
        if (pf) { CP_WAIT1(); } else { CP_WAIT0(); }
        __syncthreads();

        const uint32_t kbase = sb + AS_OFF + cur * AS_SZ;

        // ---- S = Q K^T ----
        float s[8][4];
#pragma unroll
        for (int i = 0; i < 8; i++)
#pragma unroll
            for (int r = 0; r < 4; r++) s[i][r] = 0.f;
#pragma unroll
        for (int kk = 0; kk < 4; kk++) {
            const int cb = kk * 32 + chi;
            uint32_t Kf[4][4];
#pragma unroll
            for (int bt = 0; bt < 4; bt++)
                ldsm4(Kf[bt], kbase + swz(bt * 16 + l15, cb));
#pragma unroll
            for (int nt = 0; nt < 8; nt++) {
                uint32_t bfr[2] = { Kf[nt >> 1][nt & 1], Kf[nt >> 1][(nt & 1) + 2] };
                mma16816h(s[nt], Qf[kk], bfr);
            }
        }

        // ---- mask + online softmax ----
        float mx0 = -1e30f, mx1 = -1e30f;
#pragma unroll
        for (int nt = 0; nt < 8; nt++) {
            int j0 = kt + nt * 8 + tig * 2, j1 = j0 + 1;
            float v;
            v = fminf(fmaxf(s[nt][0] * ATT_SCALE, -10000.f), 10000.f);
            v = (j0 <= row0 && j0 > row0 - WINDOW) ? v : -1e30f;
            s[nt][0] = v; mx0 = fmaxf(mx0, v);
            v = fminf(fmaxf(s[nt][1] * ATT_SCALE, -10000.f), 10000.f);
            v = (j1 <= row0 && j1 > row0 - WINDOW) ? v : -1e30f;
            s[nt][1] = v; mx0 = fmaxf(mx0, v);
            v = fminf(fmaxf(s[nt][2] * ATT_SCALE, -10000.f), 10000.f);
            v = (j0 <= row1 && j0 > row1 - WINDOW) ? v : -1e30f;
            s[nt][2] = v; mx1 = fmaxf(mx1, v);
            v = fminf(fmaxf(s[nt][3] * ATT_SCALE, -10000.f), 10000.f);
            v = (j1 <= row1 && j1 > row1 - WINDOW) ? v : -1e30f;
            s[nt][3] = v; mx1 = fmaxf(mx1, v);
        }
        mx0 = qmax(mx0); mx1 = qmax(mx1);
        const float m0n = fmaxf(m0, mx0), m1n = fmaxf(m1, mx1);
        const float c0 = __expf(m0 - m0n), c1 = __expf(m1 - m1n);

        uint32_t ph01[8], ph23[8];
        float sum0 = 0.f, sum1 = 0.f;
#pragma unroll
        for (int nt = 0; nt < 8; nt++) {
            float p0 = __expf(s[nt][0] - m0n), p1 = __expf(s[nt][1] - m0n);
            float p2 = __expf(s[nt][2] - m1n), p3 = __expf(s[nt][3] - m1n);
            sum0 += p0 + p1; sum1 += p2 + p3;
            ph01[nt] = pkh2(p0, p1);
            ph23[nt] = pkh2(p2, p3);
        }
        sum0 = qsum(sum0); sum1 = qsum(sum1);
        l0 = l0 * c0 + sum0; l1 = l1 * c1 + sum1;
        m0 = m0n; m1 = m1n;
#pragma unroll
        for (int i = 0; i < 8; i++) {
            o[i][0] *= c0; o[i][1] *= c0; o[i][2] *= c1; o[i][3] *= c1;
        }

        // ---- O += P V, V frags via ldmatrix.trans ----
#pragma unroll
        for (int kk = 0; kk < 4; kk++) {
            uint32_t pa[4] = { ph01[2 * kk], ph23[2 * kk], ph01[2 * kk + 1], ph23[2 * kk + 1] };
            uint32_t Vf[4][4];
#pragma unroll
            for (int db = 0; db < 4; db++)
                ldsm4t(Vf[db], kbase + 8192 + swz(kk * 16 + l15, db * 32 + chi));
#pragma unroll
            for (int dnt = 0; dnt < 8; dnt++) {
                uint32_t bfr[2] = { Vf[dnt >> 1][(dnt & 1) * 2], Vf[dnt >> 1][(dnt & 1) * 2 + 1] };
                mma16816h(o[dnt], pa, bfr);
            }
        }
        __syncthreads();   // all warps done with stage `cur` before refill
    }

    // ---- epilogue: normalize, store fp16 ----
    const float i0 = 1.f / l0, i1 = 1.f / l1;
    const size_t tok0 = (size_t)(b * SEQ) + row0;
#pragma unroll
    for (int dnt = 0; dnt < 8; dnt++) {
        int col = hcol + dnt * 8 + tig * 2;
        *(uint32_t*)(oh + tok0 * NEMBD + col)       = pkh2(o[dnt][0] * i0, o[dnt][1] * i0);
        *(uint32_t*)(oh + (tok0 + 8) * NEMBD + col) = pkh2(o[dnt][2] * i1, o[dnt][3] * i1);
    }
}

// ---------------------------------------------------------------------------
extern "C" void kernel_launch(void* const* d_in, const int* in_sizes, int n_in,
                              void* d_out, int out_size) {
    const float* hidden = (const float*)d_in[0];
    const float* w_attn = (const float*)d_in[1];
    const float* b_attn = (const float*)d_in[2];
    const float* w_proj = (const float*)d_in[3];
    const float* b_proj = (const float*)d_in[4];
    float* out = (float*)d_out;

    __half *kvh, *ah, *wh, *ph, *oh;
    cudaGetSymbolAddress((void**)&kvh, g_kvh);
    cudaGetSymbolAddress((void**)&ah, g_ah);
    cudaGetSymbolAddress((void**)&wh, g_wh);
    cudaGetSymbolAddress((void**)&ph, g_ph);
    cudaGetSymbolAddress((void**)&oh, g_oh);

    const int M = BATCH * SEQ;       // 4096
    const int E = NEMBD;             // 1024

    cudaFuncSetAttribute(gemm_h_kernel,
                         cudaFuncAttributeMaxDynamicSharedMemorySize, GSMEM);
    cudaFuncSetAttribute(attn_mma_kernel,
                         cudaFuncAttributeMaxDynamicSharedMemorySize, A_SMEM);

    // 0) conversions
    {
        int n4 = M * E / 4;
        cvt_h_kernel<<<(n4 + 255) / 256, 256>>>(hidden, ah, n4);
    }
    cvt_tr_h_kernel<<<dim3(3 * E / 32, E / 32), dim3(32, 8)>>>(w_attn, wh, E, 3 * E);
    cvt_tr_h_kernel<<<dim3(E / 32, E / 32), dim3(32, 8)>>>(w_proj, ph, E, E);

    // 1) QKV projection -> fp16 qkv
    gemm_h_kernel<<<dim3(3 * E / 128, M / 128), 256, GSMEM>>>(
        ah, wh, b_attn, nullptr, kvh, M, 3 * E, E);
    // 2) flash attention -> fp16
    attn_mma_kernel<<<dim3(SEQ / 64, NHEAD, BATCH), 128, A_SMEM>>>(kvh, oh);
    // 3) output projection -> fp32
    gemm_h_kernel<<<dim3(E / 128, M / 128), 256, GSMEM>>>(
        oh, ph, b_proj, out, nullptr, M, E, E);
}

// round 12
// speedup vs baseline: 2.5556x; 1.0379x over previous
#include <cuda_runtime.h>
#include <cuda_fp16.h>
#include <cstdint>

#define BATCH 2
#define SEQ 2048
#define NEMBD 1024
#define NHEAD 16
#define HDIM 64
#define WINDOW 256
#define ATT_SCALE 0.125f   // 1/sqrt(64)

// ---------------- device scratch (allocation-free rule) ----------------
__device__ __half g_kvh[(size_t)4096 * 3072];      // qkv fp16
__device__ __half g_ah[(size_t)4096 * 1024];       // hidden fp16
__device__ __half g_wh[(size_t)1024 * 3072];       // w_attn fp16 [K,N] (no transpose)
__device__ __half g_ph[(size_t)1024 * 1024];       // w_proj fp16 [K,N]
__device__ __half g_oh[(size_t)4096 * 1024];       // attn out fp16

// ---------------- helpers ----------------
__device__ __forceinline__ uint32_t smem_u32(const void* p) {
    uint32_t a;
    asm("{ .reg .u64 t; cvta.to.shared.u64 t, %1; cvt.u32.u64 %0, t; }"
        : "=r"(a) : "l"(p));
    return a;
}
__device__ __forceinline__ uint32_t pkh2(float a, float b) {
    __half2 h = __floats2half2_rn(a, b);
    return *(uint32_t*)&h;
}
__device__ __forceinline__ void mma16816h(float* c, const uint32_t* a, const uint32_t* b) {
    asm volatile(
        "mma.sync.aligned.m16n8k16.row.col.f32.f16.f16.f32 "
        "{%0,%1,%2,%3},{%4,%5,%6,%7},{%8,%9},{%0,%1,%2,%3};"
        : "+f"(c[0]), "+f"(c[1]), "+f"(c[2]), "+f"(c[3])
        : "r"(a[0]), "r"(a[1]), "r"(a[2]), "r"(a[3]), "r"(b[0]), "r"(b[1]));
}
__device__ __forceinline__ void ldsm4(uint32_t* r, uint32_t addr) {
    asm volatile("ldmatrix.sync.aligned.m8n8.x4.shared.b16 {%0,%1,%2,%3}, [%4];"
                 : "=r"(r[0]), "=r"(r[1]), "=r"(r[2]), "=r"(r[3]) : "r"(addr));
}
__device__ __forceinline__ void ldsm4t(uint32_t* r, uint32_t addr) {
    asm volatile("ldmatrix.sync.aligned.m8n8.x4.trans.shared.b16 {%0,%1,%2,%3}, [%4];"
                 : "=r"(r[0]), "=r"(r[1]), "=r"(r[2]), "=r"(r[3]) : "r"(addr));
}
__device__ __forceinline__ void cpa16(uint32_t saddr, const void* gaddr) {
    asm volatile("cp.async.cg.shared.global [%0], [%1], 16;" :: "r"(saddr), "l"(gaddr));
}
#define CP_COMMIT() asm volatile("cp.async.commit_group;")
#define CP_WAIT0()  asm volatile("cp.async.wait_group 0;")
#define CP_WAIT1()  asm volatile("cp.async.wait_group 1;")

// SW128 swizzle for 128B rows
__device__ __forceinline__ uint32_t swz(int row, int col) {
    return (uint32_t)(row * 128 + (col ^ ((row & 7) << 4)));
}
__device__ __forceinline__ float qmax(float v) {
    v = fmaxf(v, __shfl_xor_sync(0xFFFFFFFFu, v, 1));
    v = fmaxf(v, __shfl_xor_sync(0xFFFFFFFFu, v, 2));
    return v;
}
__device__ __forceinline__ float qsum(float v) {
    v += __shfl_xor_sync(0xFFFFFFFFu, v, 1);
    v += __shfl_xor_sync(0xFFFFFFFFu, v, 2);
    return v;
}

// ===========================================================================
// elementwise fp32 -> fp16 conversion (used for hidden AND weights)
// ===========================================================================
__global__ void cvt_h_kernel(const float* __restrict__ src,
                             __half* __restrict__ dst, int n4) {
    int i = blockIdx.x * blockDim.x + threadIdx.x;
    if (i < n4) {
        float4 v = *(const float4*)(src + (size_t)i * 4);
        uint2 o;
        o.x = pkh2(v.x, v.y);
        o.y = pkh2(v.z, v.w);
        *(uint2*)(dst + (size_t)i * 4) = o;
    }
}

// ===========================================================================
// single-pass fp16 GEMM: C[M,N] = A[M,K] @ B[K,N] + bias
// A row-major fp16 (K contig), B row-major fp16 [K,N] consumed via ldsm4t.
// CTA 128x128, BK=64, 2-stage cp.async, SW128, 256 threads, warp tile 64x32.
// B smem tile: [64k x 128n] as two half-buffers of 64 rows x 128B.
// If Ch != null, writes fp16 C instead of fp32.
// ===========================================================================
#define ST_A  0
#define ST_B  16384
#define ST_SZ 32768
#define GSMEM (2 * ST_SZ)

__global__ __launch_bounds__(256, 1)
void gemm_h_kernel(const __half* __restrict__ A, const __half* __restrict__ B,
                   const float* __restrict__ bias, float* __restrict__ C,
                   __half* __restrict__ Ch,
                   int M, int N, int K) {
    extern __shared__ char sm[];
    const uint32_t sb = smem_u32(sm);
    const int tid = threadIdx.x, lane = tid & 31, wid = tid >> 5;
    const int m0 = blockIdx.y * 128, n0 = blockIdx.x * 128;
    const int wm = wid >> 2, wn = wid & 3;          // 2 x 4 warp grid, tile 64x32
    const int l15 = lane & 15, chi = (lane >> 4) * 16;
    const int lrow = tid >> 3, lc = tid & 7;
    const int NT = K / 64;

    float acc[4][4][4];
#pragma unroll
    for (int i = 0; i < 4; i++)
#pragma unroll
        for (int j = 0; j < 4; j++)
#pragma unroll
            for (int r = 0; r < 4; r++) acc[i][j][r] = 0.f;

    auto load_stage = [&](int s, int kt) {
        const uint32_t sbase = sb + s * ST_SZ;
        // A: [128m x 64k], row = m, 8 chunks of 16B per row
        const size_t gk = (size_t)kt * 64 + lc * 8;
#pragma unroll
        for (int i = 0; i < 4; i++) {
            const int row = lrow + i * 32;
            cpa16(sbase + ST_A + swz(row, lc * 16), A + (size_t)(m0 + row) * K + gk);
        }
        // B: [64k x 128n], row = k, 16 chunks of 16B per 256B row -> 2 half-buffers
#pragma unroll
        for (int i = 0; i < 4; i++) {
            const int c = tid + i * 256;           // 0..1023
            const int r = c >> 4;                  // k-row 0..63
            const int nch = c & 15;                // 16B chunk within row
            const uint32_t so = ST_B + (nch >> 3) * 8192 + swz(r, (nch & 7) * 16);
            cpa16(sbase + so, B + (size_t)(kt * 64 + r) * N + n0 + nch * 8);
        }
    };

    // register double-buffered fragments
    uint32_t Af[2][4][4], Bf[2][2][4];
    auto load_frags = [&](int fb, uint32_t abase, int ks) {
        const int cb = ks * 32 + chi;
#pragma unroll
        for (int mt = 0; mt < 4; mt++)
            ldsm4(Af[fb][mt], abase + ST_A + swz(wm * 64 + mt * 16 + l15, cb));
        // B fragments via ldmatrix.trans from K-major tile
        const uint32_t bbase = abase + ST_B + (wn >> 1) * 8192;
        const int bcol = (wn & 1) * 64;
#pragma unroll
        for (int sub = 0; sub < 2; sub++)
            ldsm4t(Bf[fb][sub], bbase + swz(ks * 16 + l15, bcol + sub * 32 + chi));
    };

    load_stage(0, 0); CP_COMMIT();
    load_stage(1, 1); CP_COMMIT();

    for (int t = 0; t < NT; t++) {
        const int s = t & 1;
        CP_WAIT1();
        __syncthreads();

        const uint32_t abase = sb + s * ST_SZ;
        load_frags(0, abase, 0);
#pragma unroll
        for (int ks = 0; ks < 4; ks++) {
            const int cur = ks & 1;
            if (ks < 3) load_frags(cur ^ 1, abase, ks + 1);
#pragma unroll
            for (int mt = 0; mt < 4; mt++)
#pragma unroll
                for (int nt = 0; nt < 4; nt++) {
                    uint32_t b[2] = { Bf[cur][nt >> 1][(nt & 1) * 2],
                                      Bf[cur][nt >> 1][(nt & 1) * 2 + 1] };
                    mma16816h(acc[mt][nt], Af[cur][mt], b);
                }
        }
        __syncthreads();
        if (t + 2 < NT) { load_stage(s, t + 2); CP_COMMIT(); }
    }

    const int g = lane >> 2, tig = lane & 3;
#pragma unroll
    for (int mt = 0; mt < 4; mt++) {
#pragma unroll
        for (int nt = 0; nt < 4; nt++) {
            int row0 = m0 + wm * 64 + mt * 16 + g;
            int col  = n0 + wn * 32 + nt * 8 + tig * 2;
            float2 bb = *(const float2*)(bias + col);
            float x0 = acc[mt][nt][0] + bb.x, x1 = acc[mt][nt][1] + bb.y;
            float x2 = acc[mt][nt][2] + bb.x, x3 = acc[mt][nt][3] + bb.y;
            if (Ch) {
                *(uint32_t*)(Ch + (size_t)row0 * N + col)       = pkh2(x0, x1);
                *(uint32_t*)(Ch + (size_t)(row0 + 8) * N + col) = pkh2(x2, x3);
            } else {
                *(float2*)(C + (size_t)row0 * N + col)       = make_float2(x0, x1);
                *(float2*)(C + (size_t)(row0 + 8) * N + col) = make_float2(x2, x3);
            }
        }
    }
}

// ===========================================================================
// Flash attention, single-pass fp16 mma.sync, cp.async double-buffered K/V.
// 1 CTA = 64 queries of one (b,h); 4 warps; 128 threads. (unchanged from R11)
// ===========================================================================
#define AQ_OFF  0                              // Q staging: 8KB
#define AS_OFF  8192                           // stage s at 8192 + s*16384
#define AS_SZ   16384                          // K (8KB) + V (8KB)
#define A_SMEM  (8192 + 2 * 16384)             // 40960

__global__ __launch_bounds__(128)
void attn_mma_kernel(const __half* __restrict__ qkv, __half* __restrict__ oh) {
    extern __shared__ char sm[];
    const uint32_t sb = smem_u32(sm);
    const int b = blockIdx.z, h = blockIdx.y, qs = blockIdx.x * 64;
    const int tid = threadIdx.x, lane = tid & 31, wid = tid >> 5;
    const int l15 = lane & 15, chi = (lane >> 4) * 16;
    const int g = lane >> 2, tig = lane & 3;
    const size_t RS = 3 * NEMBD;
    const int hcol = h * HDIM;

    const int kt0 = (qs - WINDOW < 0) ? 0 : qs - WINDOW;
    const int ntiles = (qs - kt0) / 64 + 1;

    auto load_kv = [&](int s, int kt) {
        const uint32_t sbase = sb + AS_OFF + s * AS_SZ;
#pragma unroll
        for (int i = 0; i < 8; i++) {
            int idx = tid + i * 128;               // 0..1023
            int buf = idx >> 9;                    // 0 K, 1 V
            int rem = idx & 511;
            int r = rem >> 3, c = rem & 7;
            const __half* src = qkv
                + ((size_t)(b * SEQ + kt + r)) * RS + NEMBD + buf * NEMBD + hcol + c * 8;
            cpa16(sbase + buf * 8192 + swz(r, c * 16), src);
        }
    };

    load_kv(0, kt0); CP_COMMIT();
#pragma unroll
    for (int i = 0; i < 4; i++) {
        int idx = tid + i * 128;                   // 0..511
        int r = idx >> 3, c = idx & 7;
        const __half* src = qkv + ((size_t)(b * SEQ + qs + r)) * RS + hcol + c * 8;
        *(uint4*)(sm + AQ_OFF + swz(r, c * 16)) = *(const uint4*)src;
    }
    __syncthreads();
    uint32_t Qf[4][4];
#pragma unroll
    for (int kk = 0; kk < 4; kk++)
        ldsm4(Qf[kk], sb + AQ_OFF + swz(wid * 16 + l15, kk * 32 + chi));

    float o[8][4];
#pragma unroll
    for (int i = 0; i < 8; i++)
#pragma unroll
        for (int r = 0; r < 4; r++) o[i][r] = 0.f;
    float m0 = -1e30f, m1 = -1e30f, l0 = 0.f, l1 = 0.f;
    const int row0 = qs + wid * 16 + g, row1 = row0 + 8;

    for (int it = 0; it < ntiles; it++) {
        const int kt = kt0 + it * 64;
        const int cur = it & 1;
        const bool pf = (it + 1 < ntiles);
        if (pf) { load_kv(cur ^ 1, kt + 64); CP_COMMIT(); }
        if (pf) { CP_WAIT1(); } else { CP_WAIT0(); }
        __syncthreads();

        const uint32_t kbase = sb + AS_OFF + cur * AS_SZ;

        // ---- S = Q K^T ----
        float s[8][4];
#pragma unroll
        for (int i = 0; i < 8; i++)
#pragma unroll
            for (int r = 0; r < 4; r++) s[i][r] = 0.f;
#pragma unroll
        for (int kk = 0; kk < 4; kk++) {
            const int cb = kk * 32 + chi;
            uint32_t Kf[4][4];
#pragma unroll
            for (int bt = 0; bt < 4; bt++)
                ldsm4(Kf[bt], kbase + swz(bt * 16 + l15, cb));
#pragma unroll
            for (int nt = 0; nt < 8; nt++) {
                uint32_t bfr[2] = { Kf[nt >> 1][nt & 1], Kf[nt >> 1][(nt & 1) + 2] };
                mma16816h(s[nt], Qf[kk], bfr);
            }
        }

        // ---- mask + online softmax ----
        float mx0 = -1e30f, mx1 = -1e30f;
#pragma unroll
        for (int nt = 0; nt < 8; nt++) {
            int j0 = kt + nt * 8 + tig * 2, j1 = j0 + 1;
            float v;
            v = fminf(fmaxf(s[nt][0] * ATT_SCALE, -10000.f), 10000.f);
            v = (j0 <= row0 && j0 > row0 - WINDOW) ? v : -1e30f;
            s[nt][0] = v; mx0 = fmaxf(mx0, v);
            v = fminf(fmaxf(s[nt][1] * ATT_SCALE, -10000.f), 10000.f);
            v = (j1 <= row0 && j1 > row0 - WINDOW) ? v : -1e30f;
            s[nt][1] = v; mx0 = fmaxf(mx0, v);
            v = fminf(fmaxf(s[nt][2] * ATT_SCALE, -10000.f), 10000.f);
            v = (j0 <= row1 && j0 > row1 - WINDOW) ? v : -1e30f;
            s[nt][2] = v; mx1 = fmaxf(mx1, v);
            v = fminf(fmaxf(s[nt][3] * ATT_SCALE, -10000.f), 10000.f);
            v = (j1 <= row1 && j1 > row1 - WINDOW) ? v : -1e30f;
            s[nt][3] = v; mx1 = fmaxf(mx1, v);
        }
        mx0 = qmax(mx0); mx1 = qmax(mx1);
        const float m0n = fmaxf(m0, mx0), m1n = fmaxf(m1, mx1);
        const float c0 = __expf(m0 - m0n), c1 = __expf(m1 - m1n);

        uint32_t ph01[8], ph23[8];
        float sum0 = 0.f, sum1 = 0.f;
#pragma unroll
        for (int nt = 0; nt < 8; nt++) {
            float p0 = __expf(s[nt][0] - m0n), p1 = __expf(s[nt][1] - m0n);
            float p2 = __expf(s[nt][2] - m1n), p3 = __expf(s[nt][3] - m1n);
            sum0 += p0 + p1; sum1 += p2 + p3;
            ph01[nt] = pkh2(p0, p1);
            ph23[nt] = pkh2(p2, p3);
        }
        sum0 = qsum(sum0); sum1 = qsum(sum1);
        l0 = l0 * c0 + sum0; l1 = l1 * c1 + sum1;
        m0 = m0n; m1 = m1n;
#pragma unroll
        for (int i = 0; i < 8; i++) {
            o[i][0] *= c0; o[i][1] *= c0; o[i][2] *= c1; o[i][3] *= c1;
        }

        // ---- O += P V, V frags via ldmatrix.trans ----
#pragma unroll
        for (int kk = 0; kk < 4; kk++) {
            uint32_t pa[4] = { ph01[2 * kk], ph23[2 * kk], ph01[2 * kk + 1], ph23[2 * kk + 1] };
            uint32_t Vf[4][4];
#pragma unroll
            for (int db = 0; db < 4; db++)
                ldsm4t(Vf[db], kbase + 8192 + swz(kk * 16 + l15, db * 32 + chi));
#pragma unroll
            for (int dnt = 0; dnt < 8; dnt++) {
                uint32_t bfr[2] = { Vf[dnt >> 1][(dnt & 1) * 2], Vf[dnt >> 1][(dnt & 1) * 2 + 1] };
                mma16816h(o[dnt], pa, bfr);
            }
        }
        __syncthreads();
    }

    // ---- epilogue: normalize, store fp16 ----
    const float i0 = 1.f / l0, i1 = 1.f / l1;
    const size_t tok0 = (size_t)(b * SEQ) + row0;
#pragma unroll
    for (int dnt = 0; dnt < 8; dnt++) {
        int col = hcol + dnt * 8 + tig * 2;
        *(uint32_t*)(oh + tok0 * NEMBD + col)       = pkh2(o[dnt][0] * i0, o[dnt][1] * i0);
        *(uint32_t*)(oh + (tok0 + 8) * NEMBD + col) = pkh2(o[dnt][2] * i1, o[dnt][3] * i1);
    }
}

// ---------------------------------------------------------------------------
extern "C" void kernel_launch(void* const* d_in, const int* in_sizes, int n_in,
                              void* d_out, int out_size) {
    const float* hidden = (const float*)d_in[0];
    const float* w_attn = (const float*)d_in[1];
    const float* b_attn = (const float*)d_in[2];
    const float* w_proj = (const float*)d_in[3];
    const float* b_proj = (const float*)d_in[4];
    float* out = (float*)d_out;

    __half *kvh, *ah, *wh, *ph, *oh;
    cudaGetSymbolAddress((void**)&kvh, g_kvh);
    cudaGetSymbolAddress((void**)&ah, g_ah);
    cudaGetSymbolAddress((void**)&wh, g_wh);
    cudaGetSymbolAddress((void**)&ph, g_ph);
    cudaGetSymbolAddress((void**)&oh, g_oh);

    const int M = BATCH * SEQ;       // 4096
    const int E = NEMBD;             // 1024

    cudaFuncSetAttribute(gemm_h_kernel,
                         cudaFuncAttributeMaxDynamicSharedMemorySize, GSMEM);
    cudaFuncSetAttribute(attn_mma_kernel,
                         cudaFuncAttributeMaxDynamicSharedMemorySize, A_SMEM);

    // 0) conversions (all elementwise; no transposes)
    cvt_h_kernel<<<(M * E / 4 + 255) / 256, 256>>>(hidden, ah, M * E / 4);
    cvt_h_kernel<<<(E * 3 * E / 4 + 255) / 256, 256>>>(w_attn, wh, E * 3 * E / 4);
    cvt_h_kernel<<<(E * E / 4 + 255) / 256, 256>>>(w_proj, ph, E * E / 4);

    // 1) QKV projection -> fp16 qkv   (B = w_attn [K=1024, N=3072])
    gemm_h_kernel<<<dim3(3 * E / 128, M / 128), 256, GSMEM>>>(
        ah, wh, b_attn, nullptr, kvh, M, 3 * E, E);
    // 2) flash attention -> fp16
    attn_mma_kernel<<<dim3(SEQ / 64, NHEAD, BATCH), 128, A_SMEM>>>(kvh, oh);
    // 3) output projection -> fp32    (B = w_proj [K=1024, N=1024])
    gemm_h_kernel<<<dim3(E / 128, M / 128), 256, GSMEM>>>(
        oh, ph, b_proj, out, nullptr, M, E, E);
}

// round 13
// speedup vs baseline: 2.8343x; 1.1090x over previous
#include <cuda_runtime.h>
#include <cuda_fp16.h>
#include <cstdint>

#define BATCH 2
#define SEQ 2048
#define NEMBD 1024
#define NHEAD 16
#define HDIM 64
#define WINDOW 256
#define ATT_SCALE 0.125f   // 1/sqrt(64)

// ---------------- device scratch (allocation-free rule) ----------------
__device__ __half g_kvh[(size_t)4096 * 3072];      // qkv fp16
__device__ __half g_ah[(size_t)4096 * 1024];       // hidden fp16
__device__ __half g_wh[(size_t)1024 * 3072];       // w_attn fp16 [K,N]
__device__ __half g_ph[(size_t)1024 * 1024];       // w_proj fp16 [K,N]
__device__ __half g_oh[(size_t)4096 * 1024];       // attn out fp16

// ---------------- helpers ----------------
__device__ __forceinline__ uint32_t smem_u32(const void* p) {
    uint32_t a;
    asm("{ .reg .u64 t; cvta.to.shared.u64 t, %1; cvt.u32.u64 %0, t; }"
        : "=r"(a) : "l"(p));
    return a;
}
__device__ __forceinline__ uint32_t pkh2(float a, float b) {
    __half2 h = __floats2half2_rn(a, b);
    return *(uint32_t*)&h;
}
__device__ __forceinline__ void mma16816h(float* c, const uint32_t* a, const uint32_t* b) {
    asm volatile(
        "mma.sync.aligned.m16n8k16.row.col.f32.f16.f16.f32 "
        "{%0,%1,%2,%3},{%4,%5,%6,%7},{%8,%9},{%0,%1,%2,%3};"
        : "+f"(c[0]), "+f"(c[1]), "+f"(c[2]), "+f"(c[3])
        : "r"(a[0]), "r"(a[1]), "r"(a[2]), "r"(a[3]), "r"(b[0]), "r"(b[1]));
}
__device__ __forceinline__ void ldsm4(uint32_t* r, uint32_t addr) {
    asm volatile("ldmatrix.sync.aligned.m8n8.x4.shared.b16 {%0,%1,%2,%3}, [%4];"
                 : "=r"(r[0]), "=r"(r[1]), "=r"(r[2]), "=r"(r[3]) : "r"(addr));
}
__device__ __forceinline__ void ldsm4t(uint32_t* r, uint32_t addr) {
    asm volatile("ldmatrix.sync.aligned.m8n8.x4.trans.shared.b16 {%0,%1,%2,%3}, [%4];"
                 : "=r"(r[0]), "=r"(r[1]), "=r"(r[2]), "=r"(r[3]) : "r"(addr));
}
__device__ __forceinline__ void cpa16(uint32_t saddr, const void* gaddr) {
    asm volatile("cp.async.cg.shared.global [%0], [%1], 16;" :: "r"(saddr), "l"(gaddr));
}
#define CP_COMMIT() asm volatile("cp.async.commit_group;")
#define CP_WAIT0()  asm volatile("cp.async.wait_group 0;")
#define CP_WAIT1()  asm volatile("cp.async.wait_group 1;")

// SW128 swizzle for 128B rows
__device__ __forceinline__ uint32_t swz(int row, int col) {
    return (uint32_t)(row * 128 + (col ^ ((row & 7) << 4)));
}
__device__ __forceinline__ float qmax(float v) {
    v = fmaxf(v, __shfl_xor_sync(0xFFFFFFFFu, v, 1));
    v = fmaxf(v, __shfl_xor_sync(0xFFFFFFFFu, v, 2));
    return v;
}
__device__ __forceinline__ float qsum(float v) {
    v += __shfl_xor_sync(0xFFFFFFFFu, v, 1);
    v += __shfl_xor_sync(0xFFFFFFFFu, v, 2);
    return v;
}

// ===========================================================================
// merged fp32 -> fp16 conversion: hidden | w_attn | w_proj in ONE launch
// ===========================================================================
#define CVT_N1 (4096 * 1024 / 4)               // hidden float4 count
#define CVT_N2 (1024 * 3072 / 4)               // w_attn
#define CVT_N3 (1024 * 1024 / 4)               // w_proj

__global__ void cvt_all_kernel(const float* __restrict__ s1, __half* __restrict__ d1,
                               const float* __restrict__ s2, __half* __restrict__ d2,
                               const float* __restrict__ s3, __half* __restrict__ d3) {
    int i = blockIdx.x * blockDim.x + threadIdx.x;
    const float* src; __half* dst;
    if (i < CVT_N1)                { src = s1; dst = d1; }
    else if (i < CVT_N1 + CVT_N2)  { src = s2; dst = d2; i -= CVT_N1; }
    else if (i < CVT_N1 + CVT_N2 + CVT_N3) { src = s3; dst = d3; i -= CVT_N1 + CVT_N2; }
    else return;
    float4 v = *(const float4*)(src + (size_t)i * 4);
    uint2 o;
    o.x = pkh2(v.x, v.y);
    o.y = pkh2(v.z, v.w);
    *(uint2*)(dst + (size_t)i * 4) = o;
}

// ===========================================================================
// QKV GEMM: CTA 128M x 64N, BK=64, warp grid 4x2, warp tile 32x32.
// 1536 CTAs -> wave quantization 1.06 instead of 1.156.
// A row-major fp16, B row-major [K,N] via ldsm4t. Writes fp16 C.
// ===========================================================================
#define Q_ST_A  0
#define Q_ST_B  16384
#define Q_ST_SZ 24576
#define QSMEM   (2 * Q_ST_SZ)

__global__ __launch_bounds__(256, 1)
void gemm_qkv_kernel(const __half* __restrict__ A, const __half* __restrict__ B,
                     const float* __restrict__ bias, __half* __restrict__ Ch,
                     int M, int N, int K) {
    extern __shared__ char sm[];
    const uint32_t sb = smem_u32(sm);
    const int tid = threadIdx.x, lane = tid & 31, wid = tid >> 5;
    const int m0 = blockIdx.y * 128, n0 = blockIdx.x * 64;
    const int wm = wid >> 1, wn = wid & 1;          // 4 x 2 warp grid, tile 32x32
    const int l15 = lane & 15, chi = (lane >> 4) * 16;
    const int lrow = tid >> 3, lc = tid & 7;
    const int NT = K / 64;

    float acc[2][4][4];
#pragma unroll
    for (int i = 0; i < 2; i++)
#pragma unroll
        for (int j = 0; j < 4; j++)
#pragma unroll
            for (int r = 0; r < 4; r++) acc[i][j][r] = 0.f;

    auto load_stage = [&](int s, int kt) {
        const uint32_t sbase = sb + s * Q_ST_SZ;
        // A: [128m x 64k]
        const size_t gk = (size_t)kt * 64 + lc * 8;
#pragma unroll
        for (int i = 0; i < 4; i++) {
            const int row = lrow + i * 32;
            cpa16(sbase + Q_ST_A + swz(row, lc * 16), A + (size_t)(m0 + row) * K + gk);
        }
        // B: [64k x 64n] = 64 rows x 128B, 512 chunks -> 2 per thread
#pragma unroll
        for (int i = 0; i < 2; i++) {
            const int c = tid + i * 256;           // 0..511
            const int r = c >> 3;                  // k-row 0..63
            const int nch = c & 7;                 // 16B chunk
            cpa16(sbase + Q_ST_B + swz(r, nch * 16),
                  B + (size_t)(kt * 64 + r) * N + n0 + nch * 8);
        }
    };

    uint32_t Af[2][2][4], Bf[2][2][4];
    auto load_frags = [&](int fb, uint32_t abase, int ks) {
        const int cb = ks * 32 + chi;
#pragma unroll
        for (int mt = 0; mt < 2; mt++)
            ldsm4(Af[fb][mt], abase + Q_ST_A + swz(wm * 32 + mt * 16 + l15, cb));
        const int bcol = wn * 64;                  // 32 cols = 64 bytes
#pragma unroll
        for (int sub = 0; sub < 2; sub++)
            ldsm4t(Bf[fb][sub], abase + Q_ST_B + swz(ks * 16 + l15, bcol + sub * 32 + chi));
    };

    load_stage(0, 0); CP_COMMIT();
    load_stage(1, 1); CP_COMMIT();

    for (int t = 0; t < NT; t++) {
        const int s = t & 1;
        CP_WAIT1();
        __syncthreads();

        const uint32_t abase = sb + s * Q_ST_SZ;
        load_frags(0, abase, 0);
#pragma unroll
        for (int ks = 0; ks < 4; ks++) {
            const int cur = ks & 1;
            if (ks < 3) load_frags(cur ^ 1, abase, ks + 1);
#pragma unroll
            for (int mt = 0; mt < 2; mt++)
#pragma unroll
                for (int nt = 0; nt < 4; nt++) {
                    uint32_t b[2] = { Bf[cur][nt >> 1][(nt & 1) * 2],
                                      Bf[cur][nt >> 1][(nt & 1) * 2 + 1] };
                    mma16816h(acc[mt][nt], Af[cur][mt], b);
                }
        }
        __syncthreads();
        if (t + 2 < NT) { load_stage(s, t + 2); CP_COMMIT(); }
    }

    const int g = lane >> 2, tig = lane & 3;
#pragma unroll
    for (int mt = 0; mt < 2; mt++) {
#pragma unroll
        for (int nt = 0; nt < 4; nt++) {
            int row0 = m0 + wm * 32 + mt * 16 + g;
            int col  = n0 + wn * 32 + nt * 8 + tig * 2;
            float2 bb = *(const float2*)(bias + col);
            *(uint32_t*)(Ch + (size_t)row0 * N + col) =
                pkh2(acc[mt][nt][0] + bb.x, acc[mt][nt][1] + bb.y);
            *(uint32_t*)(Ch + (size_t)(row0 + 8) * N + col) =
                pkh2(acc[mt][nt][2] + bb.x, acc[mt][nt][3] + bb.y);
        }
    }
}

// ===========================================================================
// proj GEMM (R12 config, unchanged): CTA 128x128, warp tile 64x32, fp32 out.
// ===========================================================================
#define ST_A  0
#define ST_B  16384
#define ST_SZ 32768
#define GSMEM (2 * ST_SZ)

__global__ __launch_bounds__(256, 1)
void gemm_h_kernel(const __half* __restrict__ A, const __half* __restrict__ B,
                   const float* __restrict__ bias, float* __restrict__ C,
                   int M, int N, int K) {
    extern __shared__ char sm[];
    const uint32_t sb = smem_u32(sm);
    const int tid = threadIdx.x, lane = tid & 31, wid = tid >> 5;
    const int m0 = blockIdx.y * 128, n0 = blockIdx.x * 128;
    const int wm = wid >> 2, wn = wid & 3;
    const int l15 = lane & 15, chi = (lane >> 4) * 16;
    const int lrow = tid >> 3, lc = tid & 7;
    const int NT = K / 64;

    float acc[4][4][4];
#pragma unroll
    for (int i = 0; i < 4; i++)
#pragma unroll
        for (int j = 0; j < 4; j++)
#pragma unroll
            for (int r = 0; r < 4; r++) acc[i][j][r] = 0.f;

    auto load_stage = [&](int s, int kt) {
        const uint32_t sbase = sb + s * ST_SZ;
        const size_t gk = (size_t)kt * 64 + lc * 8;
#pragma unroll
        for (int i = 0; i < 4; i++) {
            const int row = lrow + i * 32;
            cpa16(sbase + ST_A + swz(row, lc * 16), A + (size_t)(m0 + row) * K + gk);
        }
#pragma unroll
        for (int i = 0; i < 4; i++) {
            const int c = tid + i * 256;
            const int r = c >> 4;
            const int nch = c & 15;
            const uint32_t so = ST_B + (nch >> 3) * 8192 + swz(r, (nch & 7) * 16);
            cpa16(sbase + so, B + (size_t)(kt * 64 + r) * N + n0 + nch * 8);
        }
    };

    uint32_t Af[2][4][4], Bf[2][2][4];
    auto load_frags = [&](int fb, uint32_t abase, int ks) {
        const int cb = ks * 32 + chi;
#pragma unroll
        for (int mt = 0; mt < 4; mt++)
            ldsm4(Af[fb][mt], abase + ST_A + swz(wm * 64 + mt * 16 + l15, cb));
        const uint32_t bbase = abase + ST_B + (wn >> 1) * 8192;
        const int bcol = (wn & 1) * 64;
#pragma unroll
        for (int sub = 0; sub < 2; sub++)
            ldsm4t(Bf[fb][sub], bbase + swz(ks * 16 + l15, bcol + sub * 32 + chi));
    };

    load_stage(0, 0); CP_COMMIT();
    load_stage(1, 1); CP_COMMIT();

    for (int t = 0; t < NT; t++) {
        const int s = t & 1;
        CP_WAIT1();
        __syncthreads();

        const uint32_t abase = sb + s * ST_SZ;
        load_frags(0, abase, 0);
#pragma unroll
        for (int ks = 0; ks < 4; ks++) {
            const int cur = ks & 1;
            if (ks < 3) load_frags(cur ^ 1, abase, ks + 1);
#pragma unroll
            for (int mt = 0; mt < 4; mt++)
#pragma unroll
                for (int nt = 0; nt < 4; nt++) {
                    uint32_t b[2] = { Bf[cur][nt >> 1][(nt & 1) * 2],
                                      Bf[cur][nt >> 1][(nt & 1) * 2 + 1] };
                    mma16816h(acc[mt][nt], Af[cur][mt], b);
                }
        }
        __syncthreads();
        if (t + 2 < NT) { load_stage(s, t + 2); CP_COMMIT(); }
    }

    const int g = lane >> 2, tig = lane & 3;
#pragma unroll
    for (int mt = 0; mt < 4; mt++) {
#pragma unroll
        for (int nt = 0; nt < 4; nt++) {
            int row0 = m0 + wm * 64 + mt * 16 + g;
            int col  = n0 + wn * 32 + nt * 8 + tig * 2;
            float2 bb = *(const float2*)(bias + col);
            *(float2*)(C + (size_t)row0 * N + col) =
                make_float2(acc[mt][nt][0] + bb.x, acc[mt][nt][1] + bb.y);
            *(float2*)(C + (size_t)(row0 + 8) * N + col) =
                make_float2(acc[mt][nt][2] + bb.x, acc[mt][nt][3] + bb.y);
        }
    }
}

// ===========================================================================
// Flash attention (unchanged from R12)
// ===========================================================================
#define AQ_OFF  0
#define AS_OFF  8192
#define AS_SZ   16384
#define A_SMEM  (8192 + 2 * 16384)

__global__ __launch_bounds__(128)
void attn_mma_kernel(const __half* __restrict__ qkv, __half* __restrict__ oh) {
    extern __shared__ char sm[];
    const uint32_t sb = smem_u32(sm);
    const int b = blockIdx.z, h = blockIdx.y, qs = blockIdx.x * 64;
    const int tid = threadIdx.x, lane = tid & 31, wid = tid >> 5;
    const int l15 = lane & 15, chi = (lane >> 4) * 16;
    const int g = lane >> 2, tig = lane & 3;
    const size_t RS = 3 * NEMBD;
    const int hcol = h * HDIM;

    const int kt0 = (qs - WINDOW < 0) ? 0 : qs - WINDOW;
    const int ntiles = (qs - kt0) / 64 + 1;

    auto load_kv = [&](int s, int kt) {
        const uint32_t sbase = sb + AS_OFF + s * AS_SZ;
#pragma unroll
        for (int i = 0; i < 8; i++) {
            int idx = tid + i * 128;
            int buf = idx >> 9;
            int rem = idx & 511;
            int r = rem >> 3, c = rem & 7;
            const __half* src = qkv
                + ((size_t)(b * SEQ + kt + r)) * RS + NEMBD + buf * NEMBD + hcol + c * 8;
            cpa16(sbase + buf * 8192 + swz(r, c * 16), src);
        }
    };

    load_kv(0, kt0); CP_COMMIT();
#pragma unroll
    for (int i = 0; i < 4; i++) {
        int idx = tid + i * 128;
        int r = idx >> 3, c = idx & 7;
        const __half* src = qkv + ((size_t)(b * SEQ + qs + r)) * RS + hcol + c * 8;
        *(uint4*)(sm + AQ_OFF + swz(r, c * 16)) = *(const uint4*)src;
    }
    __syncthreads();
    uint32_t Qf[4][4];
#pragma unroll
    for (int kk = 0; kk < 4; kk++)
        ldsm4(Qf[kk], sb + AQ_OFF + swz(wid * 16 + l15, kk * 32 + chi));

    float o[8][4];
#pragma unroll
    for (int i = 0; i < 8; i++)
#pragma unroll
        for (int r = 0; r < 4; r++) o[i][r] = 0.f;
    float m0 = -1e30f, m1 = -1e30f, l0 = 0.f, l1 = 0.f;
    const int row0 = qs + wid * 16 + g, row1 = row0 + 8;

    for (int it = 0; it < ntiles; it++) {
        const int kt = kt0 + it * 64;
        const int cur = it & 1;
        const bool pf = (it + 1 < ntiles);
        if (pf) { load_kv(cur ^ 1, kt + 64); CP_COMMIT(); }
        if (pf) { CP_WAIT1(); } else { CP_WAIT0(); }
        __syncthreads();

        const uint32_t kbase = sb + AS_OFF + cur * AS_SZ;

        float s[8][4];
#pragma unroll
        for (int i = 0; i < 8; i++)
#pragma unroll
            for (int r = 0; r < 4; r++) s[i][r] = 0.f;
#pragma unroll
        for (int kk = 0; kk < 4; kk++) {
            const int cb = kk * 32 + chi;
            uint32_t Kf[4][4];
#pragma unroll
            for (int bt = 0; bt < 4; bt++)
                ldsm4(Kf[bt], kbase + swz(bt * 16 + l15, cb));
#pragma unroll
            for (int nt = 0; nt < 8; nt++) {
                uint32_t bfr[2] = { Kf[nt >> 1][nt & 1], Kf[nt >> 1][(nt & 1) + 2] };
                mma16816h(s[nt], Qf[kk], bfr);
            }
        }

        float mx0 = -1e30f, mx1 = -1e30f;
#pragma unroll
        for (int nt = 0; nt < 8; nt++) {
            int j0 = kt + nt * 8 + tig * 2, j1 = j0 + 1;
            float v;
            v = fminf(fmaxf(s[nt][0] * ATT_SCALE, -10000.f), 10000.f);
            v = (j0 <= row0 && j0 > row0 - WINDOW) ? v : -1e30f;
            s[nt][0] = v; mx0 = fmaxf(mx0, v);
            v = fminf(fmaxf(s[nt][1] * ATT_SCALE, -10000.f), 10000.f);
            v = (j1 <= row0 && j1 > row0 - WINDOW) ? v : -1e30f;
            s[nt][1] = v; mx0 = fmaxf(mx0, v);
            v = fminf(fmaxf(s[nt][2] * ATT_SCALE, -10000.f), 10000.f);
            v = (j0 <= row1 && j0 > row1 - WINDOW) ? v : -1e30f;
            s[nt][2] = v; mx1 = fmaxf(mx1, v);
            v = fminf(fmaxf(s[nt][3] * ATT_SCALE, -10000.f), 10000.f);
            v = (j1 <= row1 && j1 > row1 - WINDOW) ? v : -1e30f;
            s[nt][3] = v; mx1 = fmaxf(mx1, v);
        }
        mx0 = qmax(mx0); mx1 = qmax(mx1);
        const float m0n = fmaxf(m0, mx0), m1n = fmaxf(m1, mx1);
        const float c0 = __expf(m0 - m0n), c1 = __expf(m1 - m1n);

        uint32_t ph01[8], ph23[8];
        float sum0 = 0.f, sum1 = 0.f;
#pragma unroll
        for (int nt = 0; nt < 8; nt++) {
            float p0 = __expf(s[nt][0] - m0n), p1 = __expf(s[nt][1] - m0n);
            float p2 = __expf(s[nt][2] - m1n), p3 = __expf(s[nt][3] - m1n);
            sum0 += p0 + p1; sum1 += p2 + p3;
            ph01[nt] = pkh2(p0, p1);
            ph23[nt] = pkh2(p2, p3);
        }
        sum0 = qsum(sum0); sum1 = qsum(sum1);
        l0 = l0 * c0 + sum0; l1 = l1 * c1 + sum1;
        m0 = m0n; m1 = m1n;
#pragma unroll
        for (int i = 0; i < 8; i++) {
            o[i][0] *= c0; o[i][1] *= c0; o[i][2] *= c1; o[i][3] *= c1;
        }

#pragma unroll
        for (int kk = 0; kk < 4; kk++) {
            uint32_t pa[4] = { ph01[2 * kk], ph23[2 * kk], ph01[2 * kk + 1], ph23[2 * kk + 1] };
            uint32_t Vf[4][4];
#pragma unroll
            for (int db = 0; db < 4; db++)
                ldsm4t(Vf[db], kbase + 8192 + swz(kk * 16 + l15, db * 32 + chi));
#pragma unroll
            for (int dnt = 0; dnt < 8; dnt++) {
                uint32_t bfr[2] = { Vf[dnt >> 1][(dnt & 1) * 2], Vf[dnt >> 1][(dnt & 1) * 2 + 1] };
                mma16816h(o[dnt], pa, bfr);
            }
        }
        __syncthreads();
    }

    const float i0 = 1.f / l0, i1 = 1.f / l1;
    const size_t tok0 = (size_t)(b * SEQ) + row0;
#pragma unroll
    for (int dnt = 0; dnt < 8; dnt++) {
        int col = hcol + dnt * 8 + tig * 2;
        *(uint32_t*)(oh + tok0 * NEMBD + col)       = pkh2(o[dnt][0] * i0, o[dnt][1] * i0);
        *(uint32_t*)(oh + (tok0 + 8) * NEMBD + col) = pkh2(o[dnt][2] * i1, o[dnt][3] * i1);
    }
}

// ---------------------------------------------------------------------------
extern "C" void kernel_launch(void* const* d_in, const int* in_sizes, int n_in,
                              void* d_out, int out_size) {
    const float* hidden = (const float*)d_in[0];
    const float* w_attn = (const float*)d_in[1];
    const float* b_attn = (const float*)d_in[2];
    const float* w_proj = (const float*)d_in[3];
    const float* b_proj = (const float*)d_in[4];
    float* out = (float*)d_out;

    __half *kvh, *ah, *wh, *ph, *oh;
    cudaGetSymbolAddress((void**)&kvh, g_kvh);
    cudaGetSymbolAddress((void**)&ah, g_ah);
    cudaGetSymbolAddress((void**)&wh, g_wh);
    cudaGetSymbolAddress((void**)&ph, g_ph);
    cudaGetSymbolAddress((void**)&oh, g_oh);

    const int M = BATCH * SEQ;       // 4096
    const int E = NEMBD;             // 1024

    cudaFuncSetAttribute(gemm_qkv_kernel,
                         cudaFuncAttributeMaxDynamicSharedMemorySize, QSMEM);
    cudaFuncSetAttribute(gemm_h_kernel,
                         cudaFuncAttributeMaxDynamicSharedMemorySize, GSMEM);
    cudaFuncSetAttribute(attn_mma_kernel,
                         cudaFuncAttributeMaxDynamicSharedMemorySize, A_SMEM);

    // 0) all conversions in one launch
    {
        int total = CVT_N1 + CVT_N2 + CVT_N3;
        cvt_all_kernel<<<(total + 255) / 256, 256>>>(hidden, ah, w_attn, wh, w_proj, ph);
    }

    // 1) QKV projection (128x64 tiles -> 1536 CTAs, quant loss 1.06)
    gemm_qkv_kernel<<<dim3(3 * E / 64, M / 128), 256, QSMEM>>>(
        ah, wh, b_attn, kvh, M, 3 * E, E);
    // 2) flash attention -> fp16
    attn_mma_kernel<<<dim3(SEQ / 64, NHEAD, BATCH), 128, A_SMEM>>>(kvh, oh);
    // 3) output projection -> fp32
    gemm_h_kernel<<<dim3(E / 128, M / 128), 256, GSMEM>>>(
        oh, ph, b_proj, out, M, E, E);
}